// round 2
// baseline (speedup 1.0000x reference)
#include <cuda_runtime.h>
#include <math.h>

#define NN 50000
#define FD 512
#define NH 4

constexpr int MAX_E2 = 8192;
constexpr int MAX_S  = 8192;
constexpr int MAX_E1 = 262144;
constexpr int MAX_U  = 262144;
constexpr int MAXDEG = 256;

// ---------------- static device scratch (no runtime allocation) ----------------
__device__ float g_ft[(size_t)NN * FD];   // ft of current layer (reused)
__device__ float g_h1[(size_t)NN * FD];   // layer-1 output h1
__device__ float g_el[NN * NH];
__device__ float g_er[NN * NH];
__device__ unsigned char g_fT[NN];
__device__ unsigned char g_fS[NN];
__device__ unsigned char g_fU[NN];
__device__ int g_E2[MAX_E2];
__device__ int g_S[MAX_S];
__device__ int g_E1[MAX_E1];
__device__ int g_U[MAX_U];
__device__ int g_nE2, g_nS, g_nE1, g_nU;

// ---------------- helpers ----------------
__device__ __forceinline__ unsigned long long dup2(float a) {
    unsigned long long r;
    unsigned int ai = __float_as_uint(a);
    asm("mov.b64 %0, {%1, %1};" : "=l"(r) : "r"(ai));
    return r;
}
__device__ __forceinline__ void fma2(unsigned long long& d, unsigned long long a, unsigned long long b) {
    asm("fma.rn.f32x2 %0, %1, %2, %0;" : "+l"(d) : "l"(a), "l"(b));
}
__device__ __forceinline__ float2 unpack2(unsigned long long v) {
    float2 r;
    r.x = __uint_as_float((unsigned int)(v & 0xffffffffull));
    r.y = __uint_as_float((unsigned int)(v >> 32));
    return r;
}
__device__ __forceinline__ float wredsum(float x) {
    #pragma unroll
    for (int o = 16; o > 0; o >>= 1) x += __shfl_xor_sync(0xffffffffu, x, o);
    return x;
}
__device__ __forceinline__ float wredmax(float x) {
    #pragma unroll
    for (int o = 16; o > 0; o >>= 1) x = fmaxf(x, __shfl_xor_sync(0xffffffffu, x, o));
    return x;
}

// ---------------- frontier construction ----------------
__global__ void k_init() {
    int i = blockIdx.x * blockDim.x + threadIdx.x;
    if (i < NN) { g_fT[i] = 0; g_fS[i] = 0; g_fU[i] = 0; }
    if (i == 0) { g_nE2 = 0; g_nS = 0; g_nE1 = 0; g_nU = 0; }
}

__global__ void k_mark(const int* __restrict__ ids, int nIds) {
    int i = threadIdx.x;
    if (i < nIds) {
        int t = ids[i];
        g_fT[t] = 1;
        g_fS[t] = 1;   // ids are part of S (need h1 there for residual + er1)
    }
}

__global__ void k_scan_e2(const int* __restrict__ src, const int* __restrict__ dst, int E) {
    for (int e = blockIdx.x * blockDim.x + threadIdx.x; e < E; e += gridDim.x * blockDim.x) {
        int d = dst[e];
        if (g_fT[d]) {
            int i = atomicAdd(&g_nE2, 1);
            if (i < MAX_E2) g_E2[i] = e;
            g_fS[src[e]] = 1;
        }
    }
}

__global__ void k_build_S() {
    int v = blockIdx.x * blockDim.x + threadIdx.x;
    if (v < NN && g_fS[v]) {
        int i = atomicAdd(&g_nS, 1);
        if (i < MAX_S) g_S[i] = v;
        g_fU[v] = 1;   // S subset of U' (need er0 at S)
    }
}

__global__ void k_scan_e1(const int* __restrict__ src, const int* __restrict__ dst, int E) {
    for (int e = blockIdx.x * blockDim.x + threadIdx.x; e < E; e += gridDim.x * blockDim.x) {
        int d = dst[e];
        if (g_fS[d]) {
            int i = atomicAdd(&g_nE1, 1);
            if (i < MAX_E1) g_E1[i] = e;
            g_fU[src[e]] = 1;
        }
    }
}

__global__ void k_build_U() {
    int v = blockIdx.x * blockDim.x + threadIdx.x;
    if (v < NN && g_fU[v]) {
        int i = atomicAdd(&g_nU, 1);
        if (i < MAX_U) g_U[i] = v;
    }
}

// ---------------- row-gathered GEMM: g_ft[rows] = A[rows] @ W  (FD x FD) ----------------
// BM=64 rows, BN=128 cols, BK=32, 256 threads, per-thread 4x8 (f32x2 packed)
constexpr int BM = 64, BN = 128, BK = 32, GT = 256;

__global__ __launch_bounds__(GT) void k_gemm(const float* __restrict__ Aext,
                                             const float* __restrict__ W, int mode) {
    __shared__ __align__(16) unsigned long long Asd[BK][BM + 2];  // duplicated A, transposed
    __shared__ __align__(16) float Ws[BK][BN];

    const float* A   = mode ? g_h1 : Aext;
    const int* rows  = mode ? g_S : g_U;
    int nRows        = mode ? min(g_nS, MAX_S) : min(g_nU, MAX_U);

    int nRT = (nRows + BM - 1) / BM;
    int nTiles = nRT * (FD / BN);
    int tid = threadIdx.x;
    int tr = tid >> 4;   // 0..15 (row group of 4)
    int tc = tid & 15;   // 0..15 (col group of 8)

    for (int t = blockIdx.x; t < nTiles; t += gridDim.x) {
        int rt = t >> 2;
        int ct = t & 3;
        int rbase = rt * BM, cbase = ct * BN;

        unsigned long long acc[4][4];
        #pragma unroll
        for (int r = 0; r < 4; r++)
            #pragma unroll
            for (int c = 0; c < 4; c++) acc[r][c] = 0ull;

        for (int kc = 0; kc < FD; kc += BK) {
            // load A chunk (gathered rows), store transposed + duplicated
            #pragma unroll
            for (int i = 0; i < (BM * BK) / GT; i++) {   // 8
                int idx = tid + i * GT;
                int r = idx >> 5;
                int kk = idx & 31;
                int gr = rbase + r;
                float a = 0.f;
                if (gr < nRows) a = A[(size_t)rows[gr] * FD + kc + kk];
                Asd[kk][r] = dup2(a);
            }
            // load W chunk
            #pragma unroll
            for (int i = 0; i < (BK * BN) / GT; i++) {   // 16
                int idx = tid + i * GT;
                int kk = idx >> 7;
                int c = idx & 127;
                Ws[kk][c] = W[(size_t)(kc + kk) * FD + cbase + c];
            }
            __syncthreads();
            #pragma unroll
            for (int kk = 0; kk < BK; kk++) {
                ulonglong2 aA = *reinterpret_cast<const ulonglong2*>(&Asd[kk][tr * 4]);
                ulonglong2 aB = *reinterpret_cast<const ulonglong2*>(&Asd[kk][tr * 4 + 2]);
                ulonglong2 bA = *reinterpret_cast<const ulonglong2*>(&Ws[kk][tc * 8]);
                ulonglong2 bB = *reinterpret_cast<const ulonglong2*>(&Ws[kk][tc * 8 + 4]);
                unsigned long long ar[4] = {aA.x, aA.y, aB.x, aB.y};
                unsigned long long bc[4] = {bA.x, bA.y, bB.x, bB.y};
                #pragma unroll
                for (int r = 0; r < 4; r++)
                    #pragma unroll
                    for (int c = 0; c < 4; c++)
                        fma2(acc[r][c], ar[r], bc[c]);
            }
            __syncthreads();
        }
        // epilogue
        #pragma unroll
        for (int r = 0; r < 4; r++) {
            int gr = rbase + tr * 4 + r;
            if (gr < nRows) {
                size_t obase = (size_t)rows[gr] * FD + cbase + tc * 8;
                float2 p0 = unpack2(acc[r][0]);
                float2 p1 = unpack2(acc[r][1]);
                float2 p2 = unpack2(acc[r][2]);
                float2 p3 = unpack2(acc[r][3]);
                float4 o0 = make_float4(p0.x, p0.y, p1.x, p1.y);
                float4 o1 = make_float4(p2.x, p2.y, p3.x, p3.y);
                *reinterpret_cast<float4*>(&g_ft[obase])     = o0;
                *reinterpret_cast<float4*>(&g_ft[obase + 4]) = o1;
            }
        }
    }
}

// ---------------- el/er: per-head dot with attention vectors ----------------
__global__ __launch_bounds__(128) void k_eler(const float* __restrict__ al,
                                              const float* __restrict__ ar, int mode) {
    const int* rows = mode ? g_S : g_U;
    int n           = mode ? min(g_nS, MAX_S) : min(g_nU, MAX_U);
    int lane = threadIdx.x & 31;
    int w = (blockIdx.x * blockDim.x + threadIdx.x) >> 5;
    int nw = (gridDim.x * blockDim.x) >> 5;
    const float4* al4 = reinterpret_cast<const float4*>(al);
    const float4* ar4 = reinterpret_cast<const float4*>(ar);
    for (int g = w; g < n; g += nw) {
        int v = rows[g];
        const float4* fp = reinterpret_cast<const float4*>(g_ft + (size_t)v * FD);
        #pragma unroll
        for (int h = 0; h < NH; h++) {
            float4 f  = fp[h * 32 + lane];
            float4 wl = al4[h * 32 + lane];
            float4 wr = ar4[h * 32 + lane];
            float sl = f.x * wl.x + f.y * wl.y + f.z * wl.z + f.w * wl.w;
            float sr = f.x * wr.x + f.y * wr.y + f.z * wr.z + f.w * wr.w;
            sl = wredsum(sl);
            sr = wredsum(sr);
            if (lane == 0) {
                g_el[v * NH + h] = sl;
                g_er[v * NH + h] = sr;
            }
        }
    }
}

// ---------------- per-dst softmax aggregation (warp per dst) ----------------
constexpr int AGG_WARPS = 4;

__global__ __launch_bounds__(AGG_WARPS * 32) void k_agg(
    const int* __restrict__ src, const int* __restrict__ dst,
    const float* __restrict__ bias, const int* __restrict__ ids, int nIds,
    float* __restrict__ outp, int mode /* 0: layer1 -> g_h1 ; 1: layer2 -> outp, +resid,+tanh */)
{
    __shared__ int   se[AGG_WARPS][MAXDEG];
    __shared__ float ssc[AGG_WARPS][MAXDEG][NH];

    const int* elist = mode ? g_E2 : g_E1;
    int nE           = mode ? min(g_nE2, MAX_E2) : min(g_nE1, MAX_E1);
    const int* dlist = mode ? ids : g_S;
    int nD           = mode ? nIds : min(g_nS, MAX_S);

    int wl = threadIdx.x >> 5;
    int lane = threadIdx.x & 31;
    int wg = blockIdx.x * AGG_WARPS + wl;
    int nwg = gridDim.x * AGG_WARPS;

    for (int g = wg; g < nD; g += nwg) {
        int v = dlist[g];
        // 1) collect matching edges into smem (warp-cooperative, list order deterministic)
        int cnt = 0;
        for (int base = 0; base < nE; base += 32) {
            int idx = base + lane;
            int e = (idx < nE) ? elist[idx] : -1;
            bool m = (e >= 0) && (dst[e] == v);
            unsigned mk = __ballot_sync(0xffffffffu, m);
            if (m) {
                int pos = cnt + __popc(mk & ((1u << lane) - 1u));
                if (pos < MAXDEG) se[wl][pos] = e;
            }
            cnt += __popc(mk);
        }
        if (cnt > MAXDEG) cnt = MAXDEG;
        __syncwarp();

        // 2) scores + per-head max
        float erv[NH], mx[NH];
        #pragma unroll
        for (int h = 0; h < NH; h++) { erv[h] = g_er[v * NH + h]; mx[h] = -1e30f; }
        for (int j = lane; j < cnt; j += 32) {
            int s = src[se[wl][j]];
            #pragma unroll
            for (int h = 0; h < NH; h++) {
                float x = g_el[s * NH + h] + erv[h];
                x = (x > 0.f) ? x : 0.2f * x;
                ssc[wl][j][h] = x;
                mx[h] = fmaxf(mx[h], x);
            }
        }
        #pragma unroll
        for (int h = 0; h < NH; h++) mx[h] = wredmax(mx[h]);
        __syncwarp();

        // 3) exp + denom
        float sm[NH] = {0.f, 0.f, 0.f, 0.f};
        for (int j = lane; j < cnt; j += 32) {
            #pragma unroll
            for (int h = 0; h < NH; h++) {
                float ex = expf(ssc[wl][j][h] - mx[h]);
                ssc[wl][j][h] = ex;
                sm[h] += ex;
            }
        }
        float inv[NH];
        #pragma unroll
        for (int h = 0; h < NH; h++) inv[h] = 1.f / wredsum(sm[h]);
        __syncwarp();

        // 4) weighted accumulation: lane owns dims [lane*16, lane*16+16)
        int h = lane >> 3;
        float invh = inv[h];
        float4 acc[4];
        #pragma unroll
        for (int i = 0; i < 4; i++) acc[i] = make_float4(0.f, 0.f, 0.f, 0.f);
        for (int j = 0; j < cnt; j++) {
            int e = se[wl][j];
            int s = src[e];
            float wgt = ssc[wl][j][h] * invh;
            const float4* fp = reinterpret_cast<const float4*>(g_ft + (size_t)s * FD + lane * 16);
            #pragma unroll
            for (int i = 0; i < 4; i++) {
                float4 f = fp[i];
                acc[i].x = fmaf(wgt, f.x, acc[i].x);
                acc[i].y = fmaf(wgt, f.y, acc[i].y);
                acc[i].z = fmaf(wgt, f.z, acc[i].z);
                acc[i].w = fmaf(wgt, f.w, acc[i].w);
            }
        }

        // 5) epilogue: (+resid) + bias, elu, (tanh), store
        size_t orow = mode ? (size_t)g * FD : (size_t)v * FD;
        float* op = (mode ? outp : g_h1) + orow + lane * 16;
        const float* bp = bias + lane * 16;
        const float* rp = mode ? (g_h1 + (size_t)v * FD + lane * 16) : nullptr;
        #pragma unroll
        for (int i = 0; i < 4; i++) {
            float4 a = acc[i];
            float4 b4 = *reinterpret_cast<const float4*>(bp + i * 4);
            if (mode) {
                float4 r4 = *reinterpret_cast<const float4*>(rp + i * 4);
                a.x += r4.x; a.y += r4.y; a.z += r4.z; a.w += r4.w;
            }
            a.x += b4.x; a.y += b4.y; a.z += b4.z; a.w += b4.w;
            a.x = (a.x > 0.f) ? a.x : expm1f(a.x);
            a.y = (a.y > 0.f) ? a.y : expm1f(a.y);
            a.z = (a.z > 0.f) ? a.z : expm1f(a.z);
            a.w = (a.w > 0.f) ? a.w : expm1f(a.w);
            if (mode) {
                a.x = tanhf(a.x); a.y = tanhf(a.y);
                a.z = tanhf(a.z); a.w = tanhf(a.w);
            }
            *reinterpret_cast<float4*>(op + i * 4) = a;
        }
    }
}

// ---------------- launch ----------------
extern "C" void kernel_launch(void* const* d_in, const int* in_sizes, int n_in,
                              void* d_out, int out_size) {
    const float* features = (const float*)d_in[0];
    const float* fc_w0    = (const float*)d_in[1];
    const float* attn_l0  = (const float*)d_in[2];
    const float* attn_r0  = (const float*)d_in[3];
    const float* bias0    = (const float*)d_in[4];
    const float* fc_w1    = (const float*)d_in[5];
    const float* attn_l1  = (const float*)d_in[6];
    const float* attn_r1  = (const float*)d_in[7];
    const float* bias1    = (const float*)d_in[8];
    const int*   src      = (const int*)d_in[9];
    const int*   dst      = (const int*)d_in[10];
    const int*   ids      = (const int*)d_in[11];
    int E    = in_sizes[9];
    int nIds = in_sizes[11];
    float* out = (float*)d_out;

    // frontier construction
    k_init<<<(NN + 255) / 256, 256>>>();
    k_mark<<<1, 32>>>(ids, nIds);
    k_scan_e2<<<2048, 256>>>(src, dst, E);
    k_build_S<<<(NN + 255) / 256, 256>>>();
    k_scan_e1<<<2048, 256>>>(src, dst, E);
    k_build_U<<<(NN + 255) / 256, 256>>>();

    // layer 1 (only at U' nodes / S dsts)
    k_gemm<<<1184, GT>>>(features, fc_w0, 0);
    k_eler<<<512, 128>>>(attn_l0, attn_r0, 0);
    k_agg<<<512, AGG_WARPS * 32>>>(src, dst, bias0, nullptr, 0, nullptr, 0);

    // layer 2 (only at S nodes / id dsts)
    k_gemm<<<256, GT>>>(nullptr, fc_w1, 1);
    k_eler<<<64, 128>>>(attn_l1, attn_r1, 1);
    k_agg<<<4, AGG_WARPS * 32>>>(src, dst, bias1, ids, nIds, out, 1);
}

// round 4
// speedup vs baseline: 2.5585x; 2.5585x over previous
#include <cuda_runtime.h>
#include <math.h>

#define NN 50000
#define FD 512
#define NH 4

constexpr int MAX_E2 = 8192;
constexpr int MAX_S  = 8192;
constexpr int MAX_U  = 262144;
constexpr int MAXDEG = 128;

// ---------------- static device scratch ----------------
__device__ float g_ft[(size_t)NN * FD];
__device__ float g_h1[(size_t)NN * FD];
__device__ float g_el[NN * NH];
__device__ float g_er[NN * NH];
__device__ unsigned char g_fS[NN];
__device__ unsigned char g_fU[NN];
__device__ int g_E2[MAX_E2];
__device__ int g_S[MAX_S];
__device__ int g_posS[NN];
__device__ int g_degS[MAX_S];
__device__ int g_bkt[(size_t)MAX_S * MAXDEG];
__device__ int g_U[MAX_U];
__device__ int g_nE2, g_nS, g_nU;

// ---------------- helpers ----------------
__device__ __forceinline__ unsigned long long dup2(float a) {
    unsigned long long r;
    unsigned int ai = __float_as_uint(a);
    asm("mov.b64 %0, {%1, %1};" : "=l"(r) : "r"(ai));
    return r;
}
__device__ __forceinline__ void fma2(unsigned long long& d, unsigned long long a, unsigned long long b) {
    asm("fma.rn.f32x2 %0, %1, %2, %0;" : "+l"(d) : "l"(a), "l"(b));
}
__device__ __forceinline__ float2 unpack2(unsigned long long v) {
    float2 r;
    r.x = __uint_as_float((unsigned int)(v & 0xffffffffull));
    r.y = __uint_as_float((unsigned int)(v >> 32));
    return r;
}
__device__ __forceinline__ float wredsum(float x) {
    #pragma unroll
    for (int o = 16; o > 0; o >>= 1) x += __shfl_xor_sync(0xffffffffu, x, o);
    return x;
}
__device__ __forceinline__ float wredmax(float x) {
    #pragma unroll
    for (int o = 16; o > 0; o >>= 1) x = fmaxf(x, __shfl_xor_sync(0xffffffffu, x, o));
    return x;
}

// ---------------- frontier construction ----------------
__global__ void k_init() {
    int i = blockIdx.x * blockDim.x + threadIdx.x;
    if (i < NN) { g_fS[i] = 0; g_fU[i] = 0; }
    if (i < MAX_S) g_degS[i] = 0;
    if (i == 0) { g_nE2 = 0; g_nS = 0; g_nU = 0; }
}

// scan for edges into target ids (self-loops guarantee ids appear as srcs too)
__global__ void k_scan_e2(const int* __restrict__ src, const int* __restrict__ dst,
                          const int* __restrict__ ids, int nIds, int E) {
    __shared__ int sids[32];
    if (threadIdx.x < nIds) sids[threadIdx.x] = ids[threadIdx.x];
    __syncthreads();
    for (int e = blockIdx.x * blockDim.x + threadIdx.x; e < E; e += gridDim.x * blockDim.x) {
        int d = dst[e];
        bool m = false;
        for (int j = 0; j < nIds; j++) m |= (d == sids[j]);
        if (m) {
            int i = atomicAdd(&g_nE2, 1);
            if (i < MAX_E2) g_E2[i] = e;
            g_fS[src[e]] = 1;
        }
    }
}

__global__ void k_build_S() {
    int v = blockIdx.x * blockDim.x + threadIdx.x;
    if (v < NN && g_fS[v]) {
        int i = atomicAdd(&g_nS, 1);
        if (i < MAX_S) { g_S[i] = v; g_posS[v] = i; }
    }
}

// scan for edges into S; bucket them per dst position
__global__ void k_scan_e1(const int* __restrict__ src, const int* __restrict__ dst, int E) {
    for (int e = blockIdx.x * blockDim.x + threadIdx.x; e < E; e += gridDim.x * blockDim.x) {
        int d = dst[e];
        if (g_fS[d]) {
            int p = g_posS[d];
            int slot = atomicAdd(&g_degS[p], 1);
            if (slot < MAXDEG) g_bkt[(size_t)p * MAXDEG + slot] = e;
            g_fU[src[e]] = 1;
        }
    }
}

__global__ void k_build_U() {
    int v = blockIdx.x * blockDim.x + threadIdx.x;
    if (v < NN && g_fU[v]) {
        int i = atomicAdd(&g_nU, 1);
        if (i < MAX_U) g_U[i] = v;
    }
}

// ---------------- row-gathered GEMM ----------------
// BM = RPT*16 rows, BN=128 cols, BK=16, 256 threads, per-thread RPT x 8 output
// (f32x2 packed accumulators), register-staged double-buffered smem.
constexpr int BN = 16 * 8, BK = 16, GT = 256;

template <int RPT>
__global__ __launch_bounds__(GT) void k_gemm(const float* __restrict__ Aext,
                                             const float* __restrict__ W, int mode) {
    constexpr int BM = RPT * 16;
    constexpr int ALD = (BM * BK) / GT;   // per-thread A elems per stage
    constexpr int WLD = (BK * BN) / GT;   // 8
    __shared__ __align__(16) float As[2][BK][BM + 4];
    __shared__ __align__(16) float Ws[2][BK][BN + 4];

    const float* A  = mode ? g_h1 : Aext;
    const int* rows = mode ? g_S : g_U;
    int nRows       = mode ? min(g_nS, MAX_S) : min(g_nU, MAX_U);

    int nRT = (nRows + BM - 1) / BM;
    int nTiles = nRT * (FD / BN);
    int tid = threadIdx.x;
    int tr = tid >> 4;    // 0..15
    int tc = tid & 15;    // 0..15

    // W load indexing (fixed per thread)
    int wc = tid & 127;
    int wk0 = tid >> 7;   // 0..1
    int woff[WLD];
    #pragma unroll
    for (int i = 0; i < WLD; i++) woff[i] = (wk0 + i * 2) * FD + wc;

    for (int t = blockIdx.x; t < nTiles; t += gridDim.x) {
        int rt = t >> 2;
        int ct = t & 3;
        int rbase = rt * BM, cbase = ct * BN;

        // per-thread gathered-row base pointers (rows tr + 16*i of this tile)
        const float* aptr[ALD];
        #pragma unroll
        for (int i = 0; i < ALD; i++) {
            int gr = rbase + tr + i * 16;
            aptr[i] = (gr < nRows) ? (A + (size_t)rows[gr] * FD) : nullptr;
        }
        const float* wbase = W + cbase;

        unsigned long long acc[RPT][4];
        #pragma unroll
        for (int r = 0; r < RPT; r++)
            #pragma unroll
            for (int c = 0; c < 4; c++) acc[r][c] = 0ull;

        float aReg[ALD], wReg[WLD];
        // preload stage 0 (kc = 0)
        #pragma unroll
        for (int i = 0; i < ALD; i++) aReg[i] = aptr[i] ? aptr[i][tc] : 0.f;
        #pragma unroll
        for (int i = 0; i < WLD; i++) wReg[i] = wbase[woff[i]];
        #pragma unroll
        for (int i = 0; i < ALD; i++) As[0][tc][tr + i * 16] = aReg[i];
        #pragma unroll
        for (int i = 0; i < WLD; i++) Ws[0][wk0 + i * 2][wc] = wReg[i];
        __syncthreads();

        int buf = 0;
        for (int kc = 0; kc < FD; kc += BK) {
            bool more = (kc + BK) < FD;
            if (more) {
                int kn = kc + BK;
                #pragma unroll
                for (int i = 0; i < ALD; i++) aReg[i] = aptr[i] ? aptr[i][kn + tc] : 0.f;
                #pragma unroll
                for (int i = 0; i < WLD; i++) wReg[i] = wbase[(size_t)kn * FD + woff[i]];
            }
            #pragma unroll
            for (int kk = 0; kk < BK; kk++) {
                unsigned long long ad[RPT];
                #pragma unroll
                for (int r = 0; r < RPT; r += 4) {
                    float4 av = *reinterpret_cast<const float4*>(&As[buf][kk][tr * RPT + r]);
                    ad[r + 0] = dup2(av.x); ad[r + 1] = dup2(av.y);
                    ad[r + 2] = dup2(av.z); ad[r + 3] = dup2(av.w);
                }
                ulonglong2 b0 = *reinterpret_cast<const ulonglong2*>(&Ws[buf][kk][tc * 8]);
                unsigned long long bp[4];
                bp[0] = b0.x; bp[1] = b0.y;
                ulonglong2 b1 = *reinterpret_cast<const ulonglong2*>(&Ws[buf][kk][tc * 8 + 4]);
                bp[2] = b1.x; bp[3] = b1.y;
                #pragma unroll
                for (int r = 0; r < RPT; r++)
                    #pragma unroll
                    for (int c = 0; c < 4; c++)
                        fma2(acc[r][c], ad[r], bp[c]);
            }
            __syncthreads();
            if (more) {
                #pragma unroll
                for (int i = 0; i < ALD; i++) As[buf ^ 1][tc][tr + i * 16] = aReg[i];
                #pragma unroll
                for (int i = 0; i < WLD; i++) Ws[buf ^ 1][wk0 + i * 2][wc] = wReg[i];
            }
            __syncthreads();
            buf ^= 1;
        }

        // epilogue
        #pragma unroll
        for (int r = 0; r < RPT; r++) {
            int gr = rbase + tr * RPT + r;
            if (gr < nRows) {
                size_t obase = (size_t)rows[gr] * FD + cbase + tc * 8;
                float2 p0 = unpack2(acc[r][0]);
                float2 p1 = unpack2(acc[r][1]);
                float2 p2 = unpack2(acc[r][2]);
                float2 p3 = unpack2(acc[r][3]);
                *reinterpret_cast<float4*>(&g_ft[obase])     = make_float4(p0.x, p0.y, p1.x, p1.y);
                *reinterpret_cast<float4*>(&g_ft[obase + 4]) = make_float4(p2.x, p2.y, p3.x, p3.y);
            }
        }
    }
}

// ---------------- el/er ----------------
__global__ __launch_bounds__(128) void k_eler(const float* __restrict__ al,
                                              const float* __restrict__ ar, int mode) {
    const int* rows = mode ? g_S : g_U;
    int n           = mode ? min(g_nS, MAX_S) : min(g_nU, MAX_U);
    int lane = threadIdx.x & 31;
    int w = (blockIdx.x * blockDim.x + threadIdx.x) >> 5;
    int nw = (gridDim.x * blockDim.x) >> 5;
    const float4* al4 = reinterpret_cast<const float4*>(al);
    const float4* ar4 = reinterpret_cast<const float4*>(ar);
    for (int g = w; g < n; g += nw) {
        int v = rows[g];
        const float4* fp = reinterpret_cast<const float4*>(g_ft + (size_t)v * FD);
        #pragma unroll
        for (int h = 0; h < NH; h++) {
            float4 f  = fp[h * 32 + lane];
            float4 wl = al4[h * 32 + lane];
            float4 wr = ar4[h * 32 + lane];
            float sl = f.x * wl.x + f.y * wl.y + f.z * wl.z + f.w * wl.w;
            float sr = f.x * wr.x + f.y * wr.y + f.z * wr.z + f.w * wr.w;
            sl = wredsum(sl);
            sr = wredsum(sr);
            if (lane == 0) {
                g_el[v * NH + h] = sl;
                g_er[v * NH + h] = sr;
            }
        }
    }
}

// ---------------- per-dst softmax aggregation ----------------
constexpr int AGG_WARPS = 4;

__global__ __launch_bounds__(AGG_WARPS * 32) void k_agg(
    const int* __restrict__ src, const int* __restrict__ dst,
    const float* __restrict__ bias, const int* __restrict__ ids, int nIds,
    float* __restrict__ outp, int mode)
{
    __shared__ int   se[AGG_WARPS][MAXDEG];     // edge ids (mode1) / unused mode0
    __shared__ int   ssrc[AGG_WARPS][MAXDEG];   // src node of each edge
    __shared__ float ssc[AGG_WARPS][MAXDEG][NH];

    int nE  = mode ? min(g_nE2, MAX_E2) : 0;
    const int* dlist = mode ? ids : g_S;
    int nD  = mode ? nIds : min(g_nS, MAX_S);

    int wl = threadIdx.x >> 5;
    int lane = threadIdx.x & 31;
    int wg = blockIdx.x * AGG_WARPS + wl;
    int nwg = gridDim.x * AGG_WARPS;

    for (int g = wg; g < nD; g += nwg) {
        int v = dlist[g];
        int cnt;
        const int* eptr;
        if (mode) {
            // collect matching edges from the small E2 list
            cnt = 0;
            for (int base = 0; base < nE; base += 32) {
                int idx = base + lane;
                int e = (idx < nE) ? g_E2[idx] : -1;
                bool m = (e >= 0) && (dst[e] == v);
                unsigned mk = __ballot_sync(0xffffffffu, m);
                if (m) {
                    int pos = cnt + __popc(mk & ((1u << lane) - 1u));
                    if (pos < MAXDEG) se[wl][pos] = e;
                }
                cnt += __popc(mk);
            }
            if (cnt > MAXDEG) cnt = MAXDEG;
            eptr = se[wl];
            __syncwarp();
        } else {
            cnt = min(g_degS[g], MAXDEG);
            eptr = &g_bkt[(size_t)g * MAXDEG];
        }

        // scores + per-head max
        float erv[NH], mx[NH];
        #pragma unroll
        for (int h = 0; h < NH; h++) { erv[h] = g_er[v * NH + h]; mx[h] = -1e30f; }
        for (int j = lane; j < cnt; j += 32) {
            int s = src[eptr[j]];
            ssrc[wl][j] = s;
            #pragma unroll
            for (int h = 0; h < NH; h++) {
                float x = g_el[s * NH + h] + erv[h];
                x = (x > 0.f) ? x : 0.2f * x;
                ssc[wl][j][h] = x;
                mx[h] = fmaxf(mx[h], x);
            }
        }
        #pragma unroll
        for (int h = 0; h < NH; h++) mx[h] = wredmax(mx[h]);
        __syncwarp();

        // exp + denom
        float sm[NH] = {0.f, 0.f, 0.f, 0.f};
        for (int j = lane; j < cnt; j += 32) {
            #pragma unroll
            for (int h = 0; h < NH; h++) {
                float ex = expf(ssc[wl][j][h] - mx[h]);
                ssc[wl][j][h] = ex;
                sm[h] += ex;
            }
        }
        float inv[NH];
        #pragma unroll
        for (int h = 0; h < NH; h++) inv[h] = 1.f / wredsum(sm[h]);
        __syncwarp();

        // weighted accumulation: lane owns dims [lane*16, lane*16+16)
        int h = lane >> 3;
        float invh = inv[h];
        float4 acc[4];
        #pragma unroll
        for (int i = 0; i < 4; i++) acc[i] = make_float4(0.f, 0.f, 0.f, 0.f);
        for (int j = 0; j < cnt; j++) {
            int s = ssrc[wl][j];
            float wgt = ssc[wl][j][h] * invh;
            const float4* fp = reinterpret_cast<const float4*>(g_ft + (size_t)s * FD + lane * 16);
            #pragma unroll
            for (int i = 0; i < 4; i++) {
                float4 f = fp[i];
                acc[i].x = fmaf(wgt, f.x, acc[i].x);
                acc[i].y = fmaf(wgt, f.y, acc[i].y);
                acc[i].z = fmaf(wgt, f.z, acc[i].z);
                acc[i].w = fmaf(wgt, f.w, acc[i].w);
            }
        }

        // epilogue
        size_t orow = mode ? (size_t)g * FD : (size_t)v * FD;
        float* op = (mode ? outp : g_h1) + orow + lane * 16;
        const float* bp = bias + lane * 16;
        const float* rp = mode ? (g_h1 + (size_t)v * FD + lane * 16) : nullptr;
        #pragma unroll
        for (int i = 0; i < 4; i++) {
            float4 a = acc[i];
            float4 b4 = *reinterpret_cast<const float4*>(bp + i * 4);
            if (mode) {
                float4 r4 = *reinterpret_cast<const float4*>(rp + i * 4);
                a.x += r4.x; a.y += r4.y; a.z += r4.z; a.w += r4.w;
            }
            a.x += b4.x; a.y += b4.y; a.z += b4.z; a.w += b4.w;
            a.x = (a.x > 0.f) ? a.x : expm1f(a.x);
            a.y = (a.y > 0.f) ? a.y : expm1f(a.y);
            a.z = (a.z > 0.f) ? a.z : expm1f(a.z);
            a.w = (a.w > 0.f) ? a.w : expm1f(a.w);
            if (mode) {
                a.x = tanhf(a.x); a.y = tanhf(a.y);
                a.z = tanhf(a.z); a.w = tanhf(a.w);
            }
            *reinterpret_cast<float4*>(op + i * 4) = a;
        }
    }
}

// ---------------- launch ----------------
extern "C" void kernel_launch(void* const* d_in, const int* in_sizes, int n_in,
                              void* d_out, int out_size) {
    const float* features = (const float*)d_in[0];
    const float* fc_w0    = (const float*)d_in[1];
    const float* attn_l0  = (const float*)d_in[2];
    const float* attn_r0  = (const float*)d_in[3];
    const float* bias0    = (const float*)d_in[4];
    const float* fc_w1    = (const float*)d_in[5];
    const float* attn_l1  = (const float*)d_in[6];
    const float* attn_r1  = (const float*)d_in[7];
    const float* bias1    = (const float*)d_in[8];
    const int*   src      = (const int*)d_in[9];
    const int*   dst      = (const int*)d_in[10];
    const int*   ids      = (const int*)d_in[11];
    int E    = in_sizes[9];
    int nIds = in_sizes[11];
    float* out = (float*)d_out;

    k_init<<<(NN + 255) / 256, 256>>>();
    k_scan_e2<<<2048, 256>>>(src, dst, ids, nIds, E);
    k_build_S<<<(NN + 255) / 256, 256>>>();
    k_scan_e1<<<2048, 256>>>(src, dst, E);
    k_build_U<<<(NN + 255) / 256, 256>>>();

    // layer 1
    k_gemm<8><<<592, GT>>>(features, fc_w0, 0);
    k_eler<<<512, 128>>>(attn_l0, attn_r0, 0);
    k_agg<<<512, AGG_WARPS * 32>>>(src, dst, bias0, nullptr, 0, nullptr, 0);

    // layer 2
    k_gemm<4><<<148, GT>>>(nullptr, fc_w1, 1);
    k_eler<<<64, 128>>>(attn_l1, attn_r1, 1);
    k_agg<<<4, AGG_WARPS * 32>>>(src, dst, bias1, ids, nIds, out, 1);
}

// round 10
// speedup vs baseline: 3.7097x; 1.4500x over previous
#include <cuda_runtime.h>
#include <math.h>

#define NN 50000
#define FD 512
#define NH 4

constexpr int MAX_E2 = 4096;
constexpr int MAX_S  = 8192;
constexpr int MAX_U  = 262144;
constexpr int MAXDEG = 128;
constexpr int MAXIDS = 32;

// ---------------- static device scratch ----------------
__device__ float4 g_el4[NN];                        // layer1 el per node (4 heads)
__device__ float4 g_er4[NN];
__device__ float  g_z[(size_t)MAX_S * NH * FD];     // per-head aggregated raw features
__device__ float  g_h1p[(size_t)MAX_S * FD];        // h1 by S-position
__device__ float4 g_el1_4[MAX_S];
__device__ float4 g_er1_4[MAX_S];
__device__ float  g_z2[(size_t)MAXIDS * NH * FD];
__device__ float4 g_wl0_4[FD], g_wr0_4[FD], g_wl1_4[FD], g_wr1_4[FD];
__device__ unsigned char g_fT[NN], g_fS[NN], g_fU[NN];
__device__ int g_E2s[MAX_E2], g_E2d[MAX_E2];
__device__ int g_S[MAX_S], g_posS[NN], g_degS[MAX_S];
__device__ int g_bkt[(size_t)MAX_S * MAXDEG];       // SRC node of each bucketed edge
__device__ int g_U[MAX_U];
__device__ int g_nE2, g_nS, g_nU;

// ---------------- helpers ----------------
__device__ __forceinline__ unsigned long long dup2(float a) {
    unsigned long long r;
    unsigned int ai = __float_as_uint(a);
    asm("mov.b64 %0, {%1, %1};" : "=l"(r) : "r"(ai));
    return r;
}
__device__ __forceinline__ void fma2(unsigned long long& d, unsigned long long a, unsigned long long b) {
    asm("fma.rn.f32x2 %0, %1, %2, %0;" : "+l"(d) : "l"(a), "l"(b));
}
__device__ __forceinline__ float2 unpack2(unsigned long long v) {
    float2 r;
    r.x = __uint_as_float((unsigned int)(v & 0xffffffffull));
    r.y = __uint_as_float((unsigned int)(v >> 32));
    return r;
}
__device__ __forceinline__ float wredsum(float x) {
    #pragma unroll
    for (int o = 16; o > 0; o >>= 1) x += __shfl_xor_sync(0xffffffffu, x, o);
    return x;
}
__device__ __forceinline__ float wredmax(float x) {
    #pragma unroll
    for (int o = 16; o > 0; o >>= 1) x = fmaxf(x, __shfl_xor_sync(0xffffffffu, x, o));
    return x;
}
__device__ __forceinline__ float eluf(float x) { return (x > 0.f) ? x : expm1f(x); }

// ---------------- frontier construction ----------------
__global__ void k_init() {
    int i = blockIdx.x * blockDim.x + threadIdx.x;
    if (i < NN) { g_fT[i] = 0; g_fS[i] = 0; g_fU[i] = 0; }
    if (i < MAX_S) g_degS[i] = 0;
    if (i == 0) { g_nE2 = 0; g_nS = 0; g_nU = 0; }
}

__global__ void k_mark(const int* __restrict__ ids, int nIds) {
    int i = threadIdx.x;
    if (i < nIds) g_fT[ids[i]] = 1;
}

__global__ void k_scan_e2(const int* __restrict__ src, const int* __restrict__ dst, int E) {
    int i = blockIdx.x * blockDim.x + threadIdx.x;
    int stride = gridDim.x * blockDim.x;
    int E4 = E >> 2;
    const int4* d4 = reinterpret_cast<const int4*>(dst);
    auto proc = [&](int dd, int e) {
        if (g_fT[dd]) {
            int s = src[e];
            int ix = atomicAdd(&g_nE2, 1);
            if (ix < MAX_E2) { g_E2s[ix] = s; g_E2d[ix] = dd; }
            g_fS[s] = 1;
        }
    };
    for (int q = i; q < E4; q += stride) {
        int4 d = d4[q];
        int e = q * 4;
        proc(d.x, e); proc(d.y, e + 1); proc(d.z, e + 2); proc(d.w, e + 3);
    }
    for (int e = E4 * 4 + i; e < E; e += stride) proc(dst[e], e);
}

__global__ void k_build_S() {
    int v = blockIdx.x * blockDim.x + threadIdx.x;
    if (v < NN && g_fS[v]) {
        int i = atomicAdd(&g_nS, 1);
        if (i < MAX_S) { g_S[i] = v; g_posS[v] = i; }
    }
}

__global__ void k_scan_e1(const int* __restrict__ src, const int* __restrict__ dst, int E) {
    int i = blockIdx.x * blockDim.x + threadIdx.x;
    int stride = gridDim.x * blockDim.x;
    int E4 = E >> 2;
    const int4* d4 = reinterpret_cast<const int4*>(dst);
    auto proc = [&](int dd, int e) {
        if (g_fS[dd]) {
            int p = g_posS[dd];
            int s = src[e];
            int slot = atomicAdd(&g_degS[p], 1);
            if (slot < MAXDEG) g_bkt[(size_t)p * MAXDEG + slot] = s;
            g_fU[s] = 1;
        }
    };
    for (int q = i; q < E4; q += stride) {
        int4 d = d4[q];
        int e = q * 4;
        proc(d.x, e); proc(d.y, e + 1); proc(d.z, e + 2); proc(d.w, e + 3);
    }
    for (int e = E4 * 4 + i; e < E; e += stride) proc(dst[e], e);
}

__global__ void k_build_U() {
    int v = blockIdx.x * blockDim.x + threadIdx.x;
    if (v < NN && g_fU[v]) {
        int i = atomicAdd(&g_nU, 1);
        if (i < MAX_U) g_U[i] = v;
    }
}

// ---------------- projected attention vectors ----------------
__global__ __launch_bounds__(128) void k_proj(const float* __restrict__ W0,
                                              const float* __restrict__ al0, const float* __restrict__ ar0,
                                              const float* __restrict__ W1,
                                              const float* __restrict__ al1, const float* __restrict__ ar1) {
    int lane = threadIdx.x & 31;
    int w = (blockIdx.x * blockDim.x + threadIdx.x) >> 5;   // k index
    if (w >= FD) return;
    const float4* w0r = reinterpret_cast<const float4*>(W0 + (size_t)w * FD);
    const float4* w1r = reinterpret_cast<const float4*>(W1 + (size_t)w * FD);
    const float4* l0 = reinterpret_cast<const float4*>(al0);
    const float4* r0 = reinterpret_cast<const float4*>(ar0);
    const float4* l1 = reinterpret_cast<const float4*>(al1);
    const float4* r1 = reinterpret_cast<const float4*>(ar1);
    float sl0[NH], sr0[NH], sl1[NH], sr1[NH];
    #pragma unroll
    for (int h = 0; h < NH; h++) {
        float4 a0 = w0r[h * 32 + lane];
        float4 b0l = l0[h * 32 + lane];
        float4 b0r = r0[h * 32 + lane];
        sl0[h] = wredsum(a0.x * b0l.x + a0.y * b0l.y + a0.z * b0l.z + a0.w * b0l.w);
        sr0[h] = wredsum(a0.x * b0r.x + a0.y * b0r.y + a0.z * b0r.z + a0.w * b0r.w);
        float4 a1 = w1r[h * 32 + lane];
        float4 b1l = l1[h * 32 + lane];
        float4 b1r = r1[h * 32 + lane];
        sl1[h] = wredsum(a1.x * b1l.x + a1.y * b1l.y + a1.z * b1l.z + a1.w * b1l.w);
        sr1[h] = wredsum(a1.x * b1r.x + a1.y * b1r.y + a1.z * b1r.z + a1.w * b1r.w);
    }
    if (lane == 0) {
        g_wl0_4[w] = make_float4(sl0[0], sl0[1], sl0[2], sl0[3]);
        g_wr0_4[w] = make_float4(sr0[0], sr0[1], sr0[2], sr0[3]);
        g_wl1_4[w] = make_float4(sl1[0], sl1[1], sl1[2], sl1[3]);
        g_wr1_4[w] = make_float4(sr1[0], sr1[1], sr1[2], sr1[3]);
    }
}

// ---------------- el/er via projected vectors ----------------
__global__ __launch_bounds__(128) void k_eler0(const float* __restrict__ X) {
    int lane = threadIdx.x & 31;
    int w = (blockIdx.x * blockDim.x + threadIdx.x) >> 5;
    int nw = (gridDim.x * blockDim.x) >> 5;
    int n = min(g_nU, MAX_U);
    for (int g = w; g < n; g += nw) {
        int v = g_U[g];
        const float4* xr = reinterpret_cast<const float4*>(X + (size_t)v * FD);
        float aL[NH] = {0, 0, 0, 0}, aR[NH] = {0, 0, 0, 0};
        #pragma unroll
        for (int i = 0; i < 4; i++) {
            float4 x4 = xr[lane * 4 + i];
            float xs[4] = {x4.x, x4.y, x4.z, x4.w};
            #pragma unroll
            for (int c = 0; c < 4; c++) {
                int k = lane * 16 + i * 4 + c;
                float4 l4 = g_wl0_4[k];
                float4 r4 = g_wr0_4[k];
                aL[0] = fmaf(xs[c], l4.x, aL[0]); aL[1] = fmaf(xs[c], l4.y, aL[1]);
                aL[2] = fmaf(xs[c], l4.z, aL[2]); aL[3] = fmaf(xs[c], l4.w, aL[3]);
                aR[0] = fmaf(xs[c], r4.x, aR[0]); aR[1] = fmaf(xs[c], r4.y, aR[1]);
                aR[2] = fmaf(xs[c], r4.z, aR[2]); aR[3] = fmaf(xs[c], r4.w, aR[3]);
            }
        }
        #pragma unroll
        for (int h = 0; h < NH; h++) { aL[h] = wredsum(aL[h]); aR[h] = wredsum(aR[h]); }
        if (lane == 0) {
            g_el4[v] = make_float4(aL[0], aL[1], aL[2], aL[3]);
            g_er4[v] = make_float4(aR[0], aR[1], aR[2], aR[3]);
        }
    }
}

__global__ __launch_bounds__(128) void k_eler1() {
    int lane = threadIdx.x & 31;
    int w = (blockIdx.x * blockDim.x + threadIdx.x) >> 5;
    int nw = (gridDim.x * blockDim.x) >> 5;
    int n = min(g_nS, MAX_S);
    for (int p = w; p < n; p += nw) {
        const float4* xr = reinterpret_cast<const float4*>(g_h1p + (size_t)p * FD);
        float aL[NH] = {0, 0, 0, 0}, aR[NH] = {0, 0, 0, 0};
        #pragma unroll
        for (int i = 0; i < 4; i++) {
            float4 x4 = xr[lane * 4 + i];
            float xs[4] = {x4.x, x4.y, x4.z, x4.w};
            #pragma unroll
            for (int c = 0; c < 4; c++) {
                int k = lane * 16 + i * 4 + c;
                float4 l4 = g_wl1_4[k];
                float4 r4 = g_wr1_4[k];
                aL[0] = fmaf(xs[c], l4.x, aL[0]); aL[1] = fmaf(xs[c], l4.y, aL[1]);
                aL[2] = fmaf(xs[c], l4.z, aL[2]); aL[3] = fmaf(xs[c], l4.w, aL[3]);
                aR[0] = fmaf(xs[c], r4.x, aR[0]); aR[1] = fmaf(xs[c], r4.y, aR[1]);
                aR[2] = fmaf(xs[c], r4.z, aR[2]); aR[3] = fmaf(xs[c], r4.w, aR[3]);
            }
        }
        #pragma unroll
        for (int h = 0; h < NH; h++) { aL[h] = wredsum(aL[h]); aR[h] = wredsum(aR[h]); }
        if (lane == 0) {
            g_el1_4[p] = make_float4(aL[0], aL[1], aL[2], aL[3]);
            g_er1_4[p] = make_float4(aR[0], aR[1], aR[2], aR[3]);
        }
    }
}

// ---------------- layer-1 aggregation of RAW features, PER HEAD ----------------
// z[p][h][k] = sum_e alpha[e,h] * X[src_e][k].  2 warp-items per dst (256 dims each).
constexpr int A1_WARPS = 4;

__global__ __launch_bounds__(A1_WARPS * 32) void k_agg1(const float* __restrict__ X) {
    __shared__ int   ssrc[A1_WARPS][MAXDEG];
    __shared__ float ssc[A1_WARPS][MAXDEG][NH];
    int wl_ = threadIdx.x >> 5, lane = threadIdx.x & 31;
    int wg = blockIdx.x * A1_WARPS + wl_;
    int nwg = gridDim.x * A1_WARPS;
    int nS = min(g_nS, MAX_S);
    int nItems = nS * 2;
    for (int it = wg; it < nItems; it += nwg) {
        int p = it >> 1, half = it & 1;
        int v = g_S[p];
        int cnt = min(g_degS[p], MAXDEG);
        float4 er4 = g_er4[v];
        float erv[NH] = {er4.x, er4.y, er4.z, er4.w};
        float mx[NH] = {-1e30f, -1e30f, -1e30f, -1e30f};
        for (int j = lane; j < cnt; j += 32) {
            int s = g_bkt[(size_t)p * MAXDEG + j];
            ssrc[wl_][j] = s;
            float4 el4 = g_el4[s];
            float es[4] = {el4.x, el4.y, el4.z, el4.w};
            #pragma unroll
            for (int h = 0; h < NH; h++) {
                float x = es[h] + erv[h];
                x = (x > 0.f) ? x : 0.2f * x;
                ssc[wl_][j][h] = x;
                mx[h] = fmaxf(mx[h], x);
            }
        }
        #pragma unroll
        for (int h = 0; h < NH; h++) mx[h] = wredmax(mx[h]);
        __syncwarp();
        float sm[NH] = {0.f, 0.f, 0.f, 0.f};
        for (int j = lane; j < cnt; j += 32) {
            #pragma unroll
            for (int h = 0; h < NH; h++) {
                float ex = expf(ssc[wl_][j][h] - mx[h]);
                ssc[wl_][j][h] = ex;
                sm[h] += ex;
            }
        }
        float inv[NH];
        #pragma unroll
        for (int h = 0; h < NH; h++) inv[h] = 1.f / wredsum(sm[h]);
        __syncwarp();

        int dbase = half * 256 + lane * 8;   // 8 dims per lane
        float4 a[NH][2];
        #pragma unroll
        for (int h = 0; h < NH; h++) { a[h][0] = make_float4(0, 0, 0, 0); a[h][1] = make_float4(0, 0, 0, 0); }
        for (int j = 0; j < cnt; j++) {
            int s = ssrc[wl_][j];
            float wh[NH];
            #pragma unroll
            for (int h = 0; h < NH; h++) wh[h] = ssc[wl_][j][h] * inv[h];
            const float4* xp = reinterpret_cast<const float4*>(X + (size_t)s * FD + dbase);
            float4 f0 = xp[0], f1 = xp[1];
            #pragma unroll
            for (int h = 0; h < NH; h++) {
                a[h][0].x = fmaf(wh[h], f0.x, a[h][0].x); a[h][0].y = fmaf(wh[h], f0.y, a[h][0].y);
                a[h][0].z = fmaf(wh[h], f0.z, a[h][0].z); a[h][0].w = fmaf(wh[h], f0.w, a[h][0].w);
                a[h][1].x = fmaf(wh[h], f1.x, a[h][1].x); a[h][1].y = fmaf(wh[h], f1.y, a[h][1].y);
                a[h][1].z = fmaf(wh[h], f1.z, a[h][1].z); a[h][1].w = fmaf(wh[h], f1.w, a[h][1].w);
            }
        }
        #pragma unroll
        for (int h = 0; h < NH; h++) {
            float* zp = g_z + ((size_t)p * NH + h) * FD + dbase;
            *reinterpret_cast<float4*>(zp)     = a[h][0];
            *reinterpret_cast<float4*>(zp + 4) = a[h][1];
        }
    }
}

// ---------------- layer-1 head-blocked GEMM: h1p[p][h*128+d] = elu(sum_k z[p][h][k]*W0[k][h*128+d] + b) ----------------
constexpr int BN = 128, BK = 16, GT = 256;

__global__ __launch_bounds__(GT) void k_gemm1(const float* __restrict__ W,
                                              const float* __restrict__ bias) {
    constexpr int RPT = 4, BM = 64, ALD = 4, WLD = 8;
    __shared__ __align__(16) float As[2][BK][BM + 4];
    __shared__ __align__(16) float Ws[2][BK][BN + 4];
    float* C = g_h1p;
    int nRows = min(g_nS, MAX_S);
    int nRT = (nRows + BM - 1) / BM;
    int nTiles = nRT * (FD / BN);
    int tid = threadIdx.x;
    int tr = tid >> 4, tc = tid & 15;
    int wc = tid & 127, wk0 = tid >> 7;
    int woff[WLD];
    #pragma unroll
    for (int i = 0; i < WLD; i++) woff[i] = (wk0 + i * 2) * FD + wc;

    for (int t = blockIdx.x; t < nTiles; t += gridDim.x) {
        int rt = t >> 2, ct = t & 3;              // ct == head
        int rbase = rt * BM, cbase = ct * BN;
        const float* aptr[ALD];
        #pragma unroll
        for (int i = 0; i < ALD; i++) {
            int gr = rbase + tr + i * 16;
            aptr[i] = (gr < nRows) ? (g_z + ((size_t)gr * NH + ct) * FD) : nullptr;
        }
        const float* wbase = W + cbase;

        unsigned long long acc[RPT][4];
        #pragma unroll
        for (int r = 0; r < RPT; r++)
            #pragma unroll
            for (int c = 0; c < 4; c++) acc[r][c] = 0ull;

        float aReg[ALD], wReg[WLD];
        #pragma unroll
        for (int i = 0; i < ALD; i++) aReg[i] = aptr[i] ? aptr[i][tc] : 0.f;
        #pragma unroll
        for (int i = 0; i < WLD; i++) wReg[i] = wbase[woff[i]];
        #pragma unroll
        for (int i = 0; i < ALD; i++) As[0][tc][tr + i * 16] = aReg[i];
        #pragma unroll
        for (int i = 0; i < WLD; i++) Ws[0][wk0 + i * 2][wc] = wReg[i];
        __syncthreads();

        int buf = 0;
        for (int kc = 0; kc < FD; kc += BK) {
            bool more = (kc + BK) < FD;
            if (more) {
                int kn = kc + BK;
                #pragma unroll
                for (int i = 0; i < ALD; i++) aReg[i] = aptr[i] ? aptr[i][kn + tc] : 0.f;
                #pragma unroll
                for (int i = 0; i < WLD; i++) wReg[i] = wbase[(size_t)kn * FD + woff[i]];
            }
            #pragma unroll
            for (int kk = 0; kk < BK; kk++) {
                float4 av = *reinterpret_cast<const float4*>(&As[buf][kk][tr * 4]);
                unsigned long long ad[4] = {dup2(av.x), dup2(av.y), dup2(av.z), dup2(av.w)};
                ulonglong2 b0 = *reinterpret_cast<const ulonglong2*>(&Ws[buf][kk][tc * 8]);
                ulonglong2 b1 = *reinterpret_cast<const ulonglong2*>(&Ws[buf][kk][tc * 8 + 4]);
                unsigned long long bp[4] = {b0.x, b0.y, b1.x, b1.y};
                #pragma unroll
                for (int r = 0; r < RPT; r++)
                    #pragma unroll
                    for (int c = 0; c < 4; c++)
                        fma2(acc[r][c], ad[r], bp[c]);
            }
            __syncthreads();
            if (more) {
                #pragma unroll
                for (int i = 0; i < ALD; i++) As[buf ^ 1][tc][tr + i * 16] = aReg[i];
                #pragma unroll
                for (int i = 0; i < WLD; i++) Ws[buf ^ 1][wk0 + i * 2][wc] = wReg[i];
            }
            __syncthreads();
            buf ^= 1;
        }

        const float4* b4 = reinterpret_cast<const float4*>(bias + cbase + tc * 8);
        float4 bb0 = b4[0], bb1 = b4[1];
        #pragma unroll
        for (int r = 0; r < RPT; r++) {
            int gr = rbase + tr * 4 + r;
            if (gr < nRows) {
                float2 p0 = unpack2(acc[r][0]);
                float2 p1 = unpack2(acc[r][1]);
                float2 p2 = unpack2(acc[r][2]);
                float2 p3 = unpack2(acc[r][3]);
                float4 o0 = make_float4(eluf(p0.x + bb0.x), eluf(p0.y + bb0.y),
                                        eluf(p1.x + bb0.z), eluf(p1.y + bb0.w));
                float4 o1 = make_float4(eluf(p2.x + bb1.x), eluf(p2.y + bb1.y),
                                        eluf(p3.x + bb1.z), eluf(p3.y + bb1.w));
                float* cp = C + (size_t)gr * FD + cbase + tc * 8;
                *reinterpret_cast<float4*>(cp)     = o0;
                *reinterpret_cast<float4*>(cp + 4) = o1;
            }
        }
    }
}

// ---------------- layer-2 aggregation, PER HEAD: z2[i][h][k] = sum alpha[e,h] * h1p[posS[src]][k] ----------------
__global__ __launch_bounds__(512) void k_agg2(const int* __restrict__ ids, int nIds) {
    __shared__ int   sps[16][MAXDEG];
    __shared__ float ssc[16][MAXDEG][NH];
    int wslot = threadIdx.x >> 5, lane = threadIdx.x & 31;
    int item = blockIdx.x * 16 + wslot;
    if (item >= nIds * 2) return;
    int i = item >> 1, half = item & 1;
    int v = ids[i];
    int pv = g_posS[v];
    int nE = min(g_nE2, MAX_E2);

    int cnt = 0;
    for (int base = 0; base < nE; base += 32) {
        int idx = base + lane;
        int d = (idx < nE) ? g_E2d[idx] : -1;
        bool m = (d == v);
        unsigned mk = __ballot_sync(0xffffffffu, m);
        if (m) {
            int pos = cnt + __popc(mk & ((1u << lane) - 1u));
            if (pos < MAXDEG) sps[wslot][pos] = g_posS[g_E2s[idx]];
        }
        cnt += __popc(mk);
    }
    if (cnt > MAXDEG) cnt = MAXDEG;
    __syncwarp();

    float4 er4 = g_er1_4[pv];
    float erv[NH] = {er4.x, er4.y, er4.z, er4.w};
    float mx[NH] = {-1e30f, -1e30f, -1e30f, -1e30f};
    for (int j = lane; j < cnt; j += 32) {
        float4 el4 = g_el1_4[sps[wslot][j]];
        float es[4] = {el4.x, el4.y, el4.z, el4.w};
        #pragma unroll
        for (int h = 0; h < NH; h++) {
            float x = es[h] + erv[h];
            x = (x > 0.f) ? x : 0.2f * x;
            ssc[wslot][j][h] = x;
            mx[h] = fmaxf(mx[h], x);
        }
    }
    #pragma unroll
    for (int h = 0; h < NH; h++) mx[h] = wredmax(mx[h]);
    __syncwarp();
    float sm[NH] = {0.f, 0.f, 0.f, 0.f};
    for (int j = lane; j < cnt; j += 32) {
        #pragma unroll
        for (int h = 0; h < NH; h++) {
            float ex = expf(ssc[wslot][j][h] - mx[h]);
            ssc[wslot][j][h] = ex;
            sm[h] += ex;
        }
    }
    float inv[NH];
    #pragma unroll
    for (int h = 0; h < NH; h++) inv[h] = 1.f / wredsum(sm[h]);
    __syncwarp();

    int dbase = half * 256 + lane * 8;
    float4 a[NH][2];
    #pragma unroll
    for (int h = 0; h < NH; h++) { a[h][0] = make_float4(0, 0, 0, 0); a[h][1] = make_float4(0, 0, 0, 0); }
    for (int j = 0; j < cnt; j++) {
        int ps = sps[wslot][j];
        float wh[NH];
        #pragma unroll
        for (int h = 0; h < NH; h++) wh[h] = ssc[wslot][j][h] * inv[h];
        const float4* fp = reinterpret_cast<const float4*>(g_h1p + (size_t)ps * FD + dbase);
        float4 f0 = fp[0], f1 = fp[1];
        #pragma unroll
        for (int h = 0; h < NH; h++) {
            a[h][0].x = fmaf(wh[h], f0.x, a[h][0].x); a[h][0].y = fmaf(wh[h], f0.y, a[h][0].y);
            a[h][0].z = fmaf(wh[h], f0.z, a[h][0].z); a[h][0].w = fmaf(wh[h], f0.w, a[h][0].w);
            a[h][1].x = fmaf(wh[h], f1.x, a[h][1].x); a[h][1].y = fmaf(wh[h], f1.y, a[h][1].y);
            a[h][1].z = fmaf(wh[h], f1.z, a[h][1].z); a[h][1].w = fmaf(wh[h], f1.w, a[h][1].w);
        }
    }
    #pragma unroll
    for (int h = 0; h < NH; h++) {
        float* zp = g_z2 + ((size_t)i * NH + h) * FD + dbase;
        *reinterpret_cast<float4*>(zp)     = a[h][0];
        *reinterpret_cast<float4*>(zp + 4) = a[h][1];
    }
}

// ---------------- final: out[i][c] = tanh(elu(sum_k z2[i][c>>7][k]*W1[k][c] + h1p[posS[id]][c] + b[c])) ----------------
__global__ __launch_bounds__(256) void k_final(const float* __restrict__ W1,
                                               const float* __restrict__ bias1,
                                               const int* __restrict__ ids, int nIds,
                                               float* __restrict__ out) {
    int c = blockIdx.x * 32 + (threadIdx.x & 31);
    int hc = c >> 7;                       // head of this output column
    int rg = threadIdx.x >> 5;             // rows rg and rg+8
    const float* wc = W1 + c;
    const float* z0 = g_z2 + ((size_t)rg * NH + hc) * FD;
    const float* z1 = g_z2 + ((size_t)(rg + 8) * NH + hc) * FD;
    float acc0 = 0.f, acc1 = 0.f;
    for (int k = 0; k < FD; k += 4) {
        float4 a = *reinterpret_cast<const float4*>(z0 + k);
        float4 b = *reinterpret_cast<const float4*>(z1 + k);
        float w0 = wc[(size_t)(k + 0) * FD];
        float w1 = wc[(size_t)(k + 1) * FD];
        float w2 = wc[(size_t)(k + 2) * FD];
        float w3 = wc[(size_t)(k + 3) * FD];
        acc0 = fmaf(a.x, w0, acc0); acc0 = fmaf(a.y, w1, acc0);
        acc0 = fmaf(a.z, w2, acc0); acc0 = fmaf(a.w, w3, acc0);
        acc1 = fmaf(b.x, w0, acc1); acc1 = fmaf(b.y, w1, acc1);
        acc1 = fmaf(b.z, w2, acc1); acc1 = fmaf(b.w, w3, acc1);
    }
    float bv = bias1[c];
    if (rg < nIds) {
        int pv = g_posS[ids[rg]];
        float x = acc0 + g_h1p[(size_t)pv * FD + c] + bv;
        out[(size_t)rg * FD + c] = tanhf(eluf(x));
    }
    int r2 = rg + 8;
    if (r2 < nIds) {
        int pv = g_posS[ids[r2]];
        float x = acc1 + g_h1p[(size_t)pv * FD + c] + bv;
        out[(size_t)r2 * FD + c] = tanhf(eluf(x));
    }
}

// ---------------- launch ----------------
extern "C" void kernel_launch(void* const* d_in, const int* in_sizes, int n_in,
                              void* d_out, int out_size) {
    const float* features = (const float*)d_in[0];
    const float* fc_w0    = (const float*)d_in[1];
    const float* attn_l0  = (const float*)d_in[2];
    const float* attn_r0  = (const float*)d_in[3];
    const float* bias0    = (const float*)d_in[4];
    const float* fc_w1    = (const float*)d_in[5];
    const float* attn_l1  = (const float*)d_in[6];
    const float* attn_r1  = (const float*)d_in[7];
    const float* bias1    = (const float*)d_in[8];
    const int*   src      = (const int*)d_in[9];
    const int*   dst      = (const int*)d_in[10];
    const int*   ids      = (const int*)d_in[11];
    int E    = in_sizes[9];
    int nIds = in_sizes[11];
    float* out = (float*)d_out;

    k_init<<<(NN + 255) / 256, 256>>>();
    k_mark<<<1, 32>>>(ids, nIds);
    k_proj<<<128, 128>>>(fc_w0, attn_l0, attn_r0, fc_w1, attn_l1, attn_r1);
    k_scan_e2<<<1024, 256>>>(src, dst, E);
    k_build_S<<<(NN + 255) / 256, 256>>>();
    k_scan_e1<<<1024, 256>>>(src, dst, E);
    k_build_U<<<(NN + 255) / 256, 256>>>();

    // layer 1: projected attention + per-head feature aggregation + head-blocked GEMM
    k_eler0<<<512, 128>>>(features);
    k_agg1<<<296, A1_WARPS * 32>>>(features);
    k_gemm1<<<96, GT>>>(fc_w0, bias0);

    // layer 2
    k_eler1<<<160, 128>>>();
    k_agg2<<<2, 512>>>(ids, nIds);
    k_final<<<16, 256>>>(fc_w1, bias1, ids, nIds, out);
}

// round 11
// speedup vs baseline: 4.7854x; 1.2900x over previous
#include <cuda_runtime.h>
#include <math.h>

#define NN 50000
#define FD 512
#define NH 4

constexpr int MAX_E2 = 4096;
constexpr int MAX_S  = 8192;
constexpr int MAX_U  = 262144;
constexpr int MAXDEG = 128;
constexpr int MAXIDS = 32;

// ---------------- static device scratch ----------------
__device__ float4 g_el4[NN];                        // layer1 el per node (4 heads)
__device__ float4 g_er4[NN];
__device__ float  g_z[(size_t)MAX_S * NH * FD];     // per-head aggregated raw features
__device__ float  g_h1p[(size_t)MAX_S * FD];        // h1 by S-position
__device__ float4 g_el1_4[MAX_S];
__device__ float4 g_er1_4[MAX_S];
__device__ float  g_z2[(size_t)MAXIDS * NH * FD];
__device__ float4 g_wl0_4[FD], g_wr0_4[FD], g_wl1_4[FD], g_wr1_4[FD];
__device__ unsigned char g_fT[NN];
__device__ int g_fSi[NN], g_fUi[NN];
__device__ int g_E2s[MAX_E2], g_E2d[MAX_E2];
__device__ int g_S[MAX_S], g_posS[NN], g_degS[MAX_S];
__device__ int g_bkt[(size_t)MAX_S * MAXDEG];       // SRC node of each bucketed edge
__device__ int g_U[MAX_U];
__device__ int g_nE2, g_nS, g_nU;

// ---------------- helpers ----------------
__device__ __forceinline__ unsigned long long dup2(float a) {
    unsigned long long r;
    unsigned int ai = __float_as_uint(a);
    asm("mov.b64 %0, {%1, %1};" : "=l"(r) : "r"(ai));
    return r;
}
__device__ __forceinline__ void fma2(unsigned long long& d, unsigned long long a, unsigned long long b) {
    asm("fma.rn.f32x2 %0, %1, %2, %0;" : "+l"(d) : "l"(a), "l"(b));
}
__device__ __forceinline__ float2 unpack2(unsigned long long v) {
    float2 r;
    r.x = __uint_as_float((unsigned int)(v & 0xffffffffull));
    r.y = __uint_as_float((unsigned int)(v >> 32));
    return r;
}
__device__ __forceinline__ float wredsum(float x) {
    #pragma unroll
    for (int o = 16; o > 0; o >>= 1) x += __shfl_xor_sync(0xffffffffu, x, o);
    return x;
}
__device__ __forceinline__ float wredmax(float x) {
    #pragma unroll
    for (int o = 16; o > 0; o >>= 1) x = fmaxf(x, __shfl_xor_sync(0xffffffffu, x, o));
    return x;
}
__device__ __forceinline__ float eluf(float x) { return (x > 0.f) ? x : expm1f(x); }

// ---------------- init: zero everything (no id marking here — done in k_proj) ----------------
__global__ void k_init() {
    int i = blockIdx.x * blockDim.x + threadIdx.x;
    if (i < NN) { g_fT[i] = 0; g_fSi[i] = 0; g_fUi[i] = 0; }
    if (i < MAX_S) {
        g_degS[i] = 0;
        g_el1_4[i] = make_float4(0, 0, 0, 0);
        g_er1_4[i] = make_float4(0, 0, 0, 0);
    }
    if (i == 0) { g_nE2 = 0; g_nS = 0; g_nU = 0; }
}

// ---------------- projected attention vectors (+ fT marking, piggybacked) ----------------
__global__ __launch_bounds__(128) void k_proj(const float* __restrict__ W0,
                                              const float* __restrict__ al0, const float* __restrict__ ar0,
                                              const float* __restrict__ W1,
                                              const float* __restrict__ al1, const float* __restrict__ ar1,
                                              const int* __restrict__ ids, int nIds) {
    if (blockIdx.x == 0 && threadIdx.x < nIds) g_fT[ids[threadIdx.x]] = 1;
    int lane = threadIdx.x & 31;
    int w = (blockIdx.x * blockDim.x + threadIdx.x) >> 5;   // k index
    if (w >= FD) return;
    const float4* w0r = reinterpret_cast<const float4*>(W0 + (size_t)w * FD);
    const float4* w1r = reinterpret_cast<const float4*>(W1 + (size_t)w * FD);
    const float4* l0 = reinterpret_cast<const float4*>(al0);
    const float4* r0 = reinterpret_cast<const float4*>(ar0);
    const float4* l1 = reinterpret_cast<const float4*>(al1);
    const float4* r1 = reinterpret_cast<const float4*>(ar1);
    float sl0[NH], sr0[NH], sl1[NH], sr1[NH];
    #pragma unroll
    for (int h = 0; h < NH; h++) {
        float4 a0 = w0r[h * 32 + lane];
        float4 b0l = l0[h * 32 + lane];
        float4 b0r = r0[h * 32 + lane];
        sl0[h] = wredsum(a0.x * b0l.x + a0.y * b0l.y + a0.z * b0l.z + a0.w * b0l.w);
        sr0[h] = wredsum(a0.x * b0r.x + a0.y * b0r.y + a0.z * b0r.z + a0.w * b0r.w);
        float4 a1 = w1r[h * 32 + lane];
        float4 b1l = l1[h * 32 + lane];
        float4 b1r = r1[h * 32 + lane];
        sl1[h] = wredsum(a1.x * b1l.x + a1.y * b1l.y + a1.z * b1l.z + a1.w * b1l.w);
        sr1[h] = wredsum(a1.x * b1r.x + a1.y * b1r.y + a1.z * b1r.z + a1.w * b1r.w);
    }
    if (lane == 0) {
        g_wl0_4[w] = make_float4(sl0[0], sl0[1], sl0[2], sl0[3]);
        g_wr0_4[w] = make_float4(sr0[0], sr0[1], sr0[2], sr0[3]);
        g_wl1_4[w] = make_float4(sl1[0], sl1[1], sl1[2], sl1[3]);
        g_wr1_4[w] = make_float4(sr1[0], sr1[1], sr1[2], sr1[3]);
    }
}

// ---------------- scan e2: find edges into ids; build S inline ----------------
__global__ void k_scan_e2(const int* __restrict__ src, const int* __restrict__ dst, int E) {
    int i = blockIdx.x * blockDim.x + threadIdx.x;
    int stride = gridDim.x * blockDim.x;
    int E4 = E >> 2;
    const int4* d4 = reinterpret_cast<const int4*>(dst);
    auto proc = [&](int dd, int e) {
        if (g_fT[dd]) {
            int s = src[e];
            int ix = atomicAdd(&g_nE2, 1);
            if (ix < MAX_E2) { g_E2s[ix] = s; g_E2d[ix] = dd; }
            if (atomicExch(&g_fSi[s], 1) == 0) {
                int p = atomicAdd(&g_nS, 1);
                if (p < MAX_S) { g_S[p] = s; g_posS[s] = p; }
            }
        }
    };
    for (int q = i; q < E4; q += stride) {
        int4 d = d4[q];
        int e = q * 4;
        proc(d.x, e); proc(d.y, e + 1); proc(d.z, e + 2); proc(d.w, e + 3);
    }
    for (int e = E4 * 4 + i; e < E; e += stride) proc(dst[e], e);
}

// ---------------- scan e1: bucket edges into S; build U inline ----------------
__global__ void k_scan_e1(const int* __restrict__ src, const int* __restrict__ dst, int E) {
    int i = blockIdx.x * blockDim.x + threadIdx.x;
    int stride = gridDim.x * blockDim.x;
    int E4 = E >> 2;
    const int4* d4 = reinterpret_cast<const int4*>(dst);
    auto proc = [&](int dd, int e) {
        if (g_fSi[dd]) {
            int p = g_posS[dd];
            int s = src[e];
            int slot = atomicAdd(&g_degS[p], 1);
            if (slot < MAXDEG) g_bkt[(size_t)p * MAXDEG + slot] = s;
            if (atomicExch(&g_fUi[s], 1) == 0) {
                int u = atomicAdd(&g_nU, 1);
                if (u < MAX_U) g_U[u] = s;
            }
        }
    };
    for (int q = i; q < E4; q += stride) {
        int4 d = d4[q];
        int e = q * 4;
        proc(d.x, e); proc(d.y, e + 1); proc(d.z, e + 2); proc(d.w, e + 3);
    }
    for (int e = E4 * 4 + i; e < E; e += stride) proc(dst[e], e);
}

// ---------------- el/er for layer 1 over U (smem-staged tables) ----------------
__global__ __launch_bounds__(256) void k_eler0(const float* __restrict__ X) {
    __shared__ float4 swl[FD], swr[FD];
    for (int k = threadIdx.x; k < FD; k += 256) { swl[k] = g_wl0_4[k]; swr[k] = g_wr0_4[k]; }
    __syncthreads();
    int lane = threadIdx.x & 31;
    int w = (blockIdx.x * blockDim.x + threadIdx.x) >> 5;
    int nw = (gridDim.x * blockDim.x) >> 5;
    int n = min(g_nU, MAX_U);
    for (int g = w; g < n; g += nw) {
        int v = g_U[g];
        const float4* xr = reinterpret_cast<const float4*>(X + (size_t)v * FD);
        float aL[NH] = {0, 0, 0, 0}, aR[NH] = {0, 0, 0, 0};
        #pragma unroll
        for (int i = 0; i < 4; i++) {
            float4 x4 = xr[lane * 4 + i];
            float xs[4] = {x4.x, x4.y, x4.z, x4.w};
            #pragma unroll
            for (int c = 0; c < 4; c++) {
                int k = lane * 16 + i * 4 + c;
                float4 l4 = swl[k];
                float4 r4 = swr[k];
                aL[0] = fmaf(xs[c], l4.x, aL[0]); aL[1] = fmaf(xs[c], l4.y, aL[1]);
                aL[2] = fmaf(xs[c], l4.z, aL[2]); aL[3] = fmaf(xs[c], l4.w, aL[3]);
                aR[0] = fmaf(xs[c], r4.x, aR[0]); aR[1] = fmaf(xs[c], r4.y, aR[1]);
                aR[2] = fmaf(xs[c], r4.z, aR[2]); aR[3] = fmaf(xs[c], r4.w, aR[3]);
            }
        }
        #pragma unroll
        for (int h = 0; h < NH; h++) { aL[h] = wredsum(aL[h]); aR[h] = wredsum(aR[h]); }
        if (lane == 0) {
            g_el4[v] = make_float4(aL[0], aL[1], aL[2], aL[3]);
            g_er4[v] = make_float4(aR[0], aR[1], aR[2], aR[3]);
        }
    }
}

// ---------------- layer-1 per-head aggregation; block = 4 dsts, scores shared ----------------
__global__ __launch_bounds__(256) void k_agg1(const float* __restrict__ X) {
    __shared__ int   ssrc[4][MAXDEG];
    __shared__ float ssc[4][MAXDEG][NH];
    __shared__ float sinv[4][NH];
    int w = threadIdx.x >> 5, lane = threadIdx.x & 31;
    int nS = min(g_nS, MAX_S);
    int nGrp = (nS + 3) >> 2;
    for (int grp = blockIdx.x; grp < nGrp; grp += gridDim.x) {
        // Phase A: warps 0..3 compute scores + softmax for dst grp*4+w
        if (w < 4) {
            int p = grp * 4 + w;
            if (p < nS) {
                int v = g_S[p];
                int cnt = min(g_degS[p], MAXDEG);
                float4 er4 = g_er4[v];
                float erv[NH] = {er4.x, er4.y, er4.z, er4.w};
                float mx[NH] = {-1e30f, -1e30f, -1e30f, -1e30f};
                for (int j = lane; j < cnt; j += 32) {
                    int s = g_bkt[(size_t)p * MAXDEG + j];
                    ssrc[w][j] = s;
                    float4 el4 = g_el4[s];
                    float es[4] = {el4.x, el4.y, el4.z, el4.w};
                    #pragma unroll
                    for (int h = 0; h < NH; h++) {
                        float x = es[h] + erv[h];
                        x = (x > 0.f) ? x : 0.2f * x;
                        ssc[w][j][h] = x;
                        mx[h] = fmaxf(mx[h], x);
                    }
                }
                #pragma unroll
                for (int h = 0; h < NH; h++) mx[h] = wredmax(mx[h]);
                __syncwarp();
                float sm[NH] = {0.f, 0.f, 0.f, 0.f};
                for (int j = lane; j < cnt; j += 32) {
                    #pragma unroll
                    for (int h = 0; h < NH; h++) {
                        float ex = expf(ssc[w][j][h] - mx[h]);
                        ssc[w][j][h] = ex;
                        sm[h] += ex;
                    }
                }
                #pragma unroll
                for (int h = 0; h < NH; h++) {
                    float s = wredsum(sm[h]);
                    if (lane == 0) sinv[w][h] = 1.f / s;
                }
            }
        }
        __syncthreads();
        // Phase B: all 8 warps accumulate; warp w -> dst grp*4+(w>>1), half w&1
        {
            int slot = w >> 1;
            int p = grp * 4 + slot;
            if (p < nS) {
                int half = w & 1;
                int cnt = min(g_degS[p], MAXDEG);
                float inv[NH];
                #pragma unroll
                for (int h = 0; h < NH; h++) inv[h] = sinv[slot][h];
                int dbase = half * 256 + lane * 8;
                float4 a[NH][2];
                #pragma unroll
                for (int h = 0; h < NH; h++) { a[h][0] = make_float4(0, 0, 0, 0); a[h][1] = make_float4(0, 0, 0, 0); }
                for (int j = 0; j < cnt; j++) {
                    int s = ssrc[slot][j];
                    float wh[NH];
                    #pragma unroll
                    for (int h = 0; h < NH; h++) wh[h] = ssc[slot][j][h] * inv[h];
                    const float4* xp = reinterpret_cast<const float4*>(X + (size_t)s * FD + dbase);
                    float4 f0 = xp[0], f1 = xp[1];
                    #pragma unroll
                    for (int h = 0; h < NH; h++) {
                        a[h][0].x = fmaf(wh[h], f0.x, a[h][0].x); a[h][0].y = fmaf(wh[h], f0.y, a[h][0].y);
                        a[h][0].z = fmaf(wh[h], f0.z, a[h][0].z); a[h][0].w = fmaf(wh[h], f0.w, a[h][0].w);
                        a[h][1].x = fmaf(wh[h], f1.x, a[h][1].x); a[h][1].y = fmaf(wh[h], f1.y, a[h][1].y);
                        a[h][1].z = fmaf(wh[h], f1.z, a[h][1].z); a[h][1].w = fmaf(wh[h], f1.w, a[h][1].w);
                    }
                }
                #pragma unroll
                for (int h = 0; h < NH; h++) {
                    float* zp = g_z + ((size_t)p * NH + h) * FD + dbase;
                    *reinterpret_cast<float4*>(zp)     = a[h][0];
                    *reinterpret_cast<float4*>(zp + 4) = a[h][1];
                }
            }
        }
        __syncthreads();
    }
}

// ---------------- layer-1 head-blocked GEMM + fused el1/er1 epilogue ----------------
constexpr int BN = 128, BK = 16, GT = 256;

__global__ __launch_bounds__(GT) void k_gemm1(const float* __restrict__ W,
                                              const float* __restrict__ bias) {
    constexpr int RPT = 4, BM = 64, ALD = 4, WLD = 8;
    __shared__ __align__(16) float As[2][BK][BM + 4];
    __shared__ __align__(16) float Ws[2][BK][BN + 4];
    float* C = g_h1p;
    int nRows = min(g_nS, MAX_S);
    int nRT = (nRows + BM - 1) / BM;
    int nTiles = nRT * (FD / BN);
    int tid = threadIdx.x;
    int tr = tid >> 4, tc = tid & 15;
    int wc = tid & 127, wk0 = tid >> 7;
    int woff[WLD];
    #pragma unroll
    for (int i = 0; i < WLD; i++) woff[i] = (wk0 + i * 2) * FD + wc;

    for (int t = blockIdx.x; t < nTiles; t += gridDim.x) {
        int rt = t >> 2, ct = t & 3;              // ct == head
        int rbase = rt * BM, cbase = ct * BN;
        const float* aptr[ALD];
        #pragma unroll
        for (int i = 0; i < ALD; i++) {
            int gr = rbase + tr + i * 16;
            aptr[i] = (gr < nRows) ? (g_z + ((size_t)gr * NH + ct) * FD) : nullptr;
        }
        const float* wbase = W + cbase;

        unsigned long long acc[RPT][4];
        #pragma unroll
        for (int r = 0; r < RPT; r++)
            #pragma unroll
            for (int c = 0; c < 4; c++) acc[r][c] = 0ull;

        float aReg[ALD], wReg[WLD];
        #pragma unroll
        for (int i = 0; i < ALD; i++) aReg[i] = aptr[i] ? aptr[i][tc] : 0.f;
        #pragma unroll
        for (int i = 0; i < WLD; i++) wReg[i] = wbase[woff[i]];
        #pragma unroll
        for (int i = 0; i < ALD; i++) As[0][tc][tr + i * 16] = aReg[i];
        #pragma unroll
        for (int i = 0; i < WLD; i++) Ws[0][wk0 + i * 2][wc] = wReg[i];
        __syncthreads();

        int buf = 0;
        for (int kc = 0; kc < FD; kc += BK) {
            bool more = (kc + BK) < FD;
            if (more) {
                int kn = kc + BK;
                #pragma unroll
                for (int i = 0; i < ALD; i++) aReg[i] = aptr[i] ? aptr[i][kn + tc] : 0.f;
                #pragma unroll
                for (int i = 0; i < WLD; i++) wReg[i] = wbase[(size_t)kn * FD + woff[i]];
            }
            #pragma unroll
            for (int kk = 0; kk < BK; kk++) {
                float4 av = *reinterpret_cast<const float4*>(&As[buf][kk][tr * 4]);
                unsigned long long ad[4] = {dup2(av.x), dup2(av.y), dup2(av.z), dup2(av.w)};
                ulonglong2 b0 = *reinterpret_cast<const ulonglong2*>(&Ws[buf][kk][tc * 8]);
                ulonglong2 b1 = *reinterpret_cast<const ulonglong2*>(&Ws[buf][kk][tc * 8 + 4]);
                unsigned long long bp[4] = {b0.x, b0.y, b1.x, b1.y};
                #pragma unroll
                for (int r = 0; r < RPT; r++)
                    #pragma unroll
                    for (int c = 0; c < 4; c++)
                        fma2(acc[r][c], ad[r], bp[c]);
            }
            __syncthreads();
            if (more) {
                #pragma unroll
                for (int i = 0; i < ALD; i++) As[buf ^ 1][tc][tr + i * 16] = aReg[i];
                #pragma unroll
                for (int i = 0; i < WLD; i++) Ws[buf ^ 1][wk0 + i * 2][wc] = wReg[i];
            }
            __syncthreads();
            buf ^= 1;
        }

        // epilogue: bias+elu store, plus fused el1/er1 partial dots
        const float4* b4 = reinterpret_cast<const float4*>(bias + cbase + tc * 8);
        float4 bb0 = b4[0], bb1 = b4[1];
        float4 wl[8], wr[8];
        #pragma unroll
        for (int i = 0; i < 8; i++) {
            wl[i] = g_wl1_4[cbase + tc * 8 + i];
            wr[i] = g_wr1_4[cbase + tc * 8 + i];
        }
        #pragma unroll
        for (int r = 0; r < RPT; r++) {
            int gr = rbase + tr * 4 + r;
            if (gr < nRows) {
                float2 p0 = unpack2(acc[r][0]);
                float2 p1 = unpack2(acc[r][1]);
                float2 p2 = unpack2(acc[r][2]);
                float2 p3 = unpack2(acc[r][3]);
                float vals[8] = {eluf(p0.x + bb0.x), eluf(p0.y + bb0.y),
                                 eluf(p1.x + bb0.z), eluf(p1.y + bb0.w),
                                 eluf(p2.x + bb1.x), eluf(p2.y + bb1.y),
                                 eluf(p3.x + bb1.z), eluf(p3.y + bb1.w)};
                float* cp = C + (size_t)gr * FD + cbase + tc * 8;
                *reinterpret_cast<float4*>(cp)     = make_float4(vals[0], vals[1], vals[2], vals[3]);
                *reinterpret_cast<float4*>(cp + 4) = make_float4(vals[4], vals[5], vals[6], vals[7]);
                float l0 = 0, l1 = 0, l2 = 0, l3 = 0, r0 = 0, r1 = 0, r2 = 0, r3 = 0;
                #pragma unroll
                for (int i = 0; i < 8; i++) {
                    l0 = fmaf(vals[i], wl[i].x, l0); l1 = fmaf(vals[i], wl[i].y, l1);
                    l2 = fmaf(vals[i], wl[i].z, l2); l3 = fmaf(vals[i], wl[i].w, l3);
                    r0 = fmaf(vals[i], wr[i].x, r0); r1 = fmaf(vals[i], wr[i].y, r1);
                    r2 = fmaf(vals[i], wr[i].z, r2); r3 = fmaf(vals[i], wr[i].w, r3);
                }
                float* elp = reinterpret_cast<float*>(&g_el1_4[gr]);
                float* erp = reinterpret_cast<float*>(&g_er1_4[gr]);
                atomicAdd(elp + 0, l0); atomicAdd(elp + 1, l1);
                atomicAdd(elp + 2, l2); atomicAdd(elp + 3, l3);
                atomicAdd(erp + 0, r0); atomicAdd(erp + 1, r1);
                atomicAdd(erp + 2, r2); atomicAdd(erp + 3, r3);
            }
        }
    }
}

// ---------------- layer-2 per-head aggregation ----------------
__global__ __launch_bounds__(512) void k_agg2(const int* __restrict__ ids, int nIds) {
    __shared__ int   sps[16][MAXDEG];
    __shared__ float ssc[16][MAXDEG][NH];
    int wslot = threadIdx.x >> 5, lane = threadIdx.x & 31;
    int item = blockIdx.x * 16 + wslot;
    if (item >= nIds * 2) return;
    int i = item >> 1, half = item & 1;
    int v = ids[i];
    int pv = g_posS[v];
    int nE = min(g_nE2, MAX_E2);

    int cnt = 0;
    for (int base = 0; base < nE; base += 32) {
        int idx = base + lane;
        int d = (idx < nE) ? g_E2d[idx] : -1;
        bool m = (d == v);
        unsigned mk = __ballot_sync(0xffffffffu, m);
        if (m) {
            int pos = cnt + __popc(mk & ((1u << lane) - 1u));
            if (pos < MAXDEG) sps[wslot][pos] = g_posS[g_E2s[idx]];
        }
        cnt += __popc(mk);
    }
    if (cnt > MAXDEG) cnt = MAXDEG;
    __syncwarp();

    float4 er4 = g_er1_4[pv];
    float erv[NH] = {er4.x, er4.y, er4.z, er4.w};
    float mx[NH] = {-1e30f, -1e30f, -1e30f, -1e30f};
    for (int j = lane; j < cnt; j += 32) {
        float4 el4 = g_el1_4[sps[wslot][j]];
        float es[4] = {el4.x, el4.y, el4.z, el4.w};
        #pragma unroll
        for (int h = 0; h < NH; h++) {
            float x = es[h] + erv[h];
            x = (x > 0.f) ? x : 0.2f * x;
            ssc[wslot][j][h] = x;
            mx[h] = fmaxf(mx[h], x);
        }
    }
    #pragma unroll
    for (int h = 0; h < NH; h++) mx[h] = wredmax(mx[h]);
    __syncwarp();
    float sm[NH] = {0.f, 0.f, 0.f, 0.f};
    for (int j = lane; j < cnt; j += 32) {
        #pragma unroll
        for (int h = 0; h < NH; h++) {
            float ex = expf(ssc[wslot][j][h] - mx[h]);
            ssc[wslot][j][h] = ex;
            sm[h] += ex;
        }
    }
    float inv[NH];
    #pragma unroll
    for (int h = 0; h < NH; h++) inv[h] = 1.f / wredsum(sm[h]);
    __syncwarp();

    int dbase = half * 256 + lane * 8;
    float4 a[NH][2];
    #pragma unroll
    for (int h = 0; h < NH; h++) { a[h][0] = make_float4(0, 0, 0, 0); a[h][1] = make_float4(0, 0, 0, 0); }
    for (int j = 0; j < cnt; j++) {
        int ps = sps[wslot][j];
        float wh[NH];
        #pragma unroll
        for (int h = 0; h < NH; h++) wh[h] = ssc[wslot][j][h] * inv[h];
        const float4* fp = reinterpret_cast<const float4*>(g_h1p + (size_t)ps * FD + dbase);
        float4 f0 = fp[0], f1 = fp[1];
        #pragma unroll
        for (int h = 0; h < NH; h++) {
            a[h][0].x = fmaf(wh[h], f0.x, a[h][0].x); a[h][0].y = fmaf(wh[h], f0.y, a[h][0].y);
            a[h][0].z = fmaf(wh[h], f0.z, a[h][0].z); a[h][0].w = fmaf(wh[h], f0.w, a[h][0].w);
            a[h][1].x = fmaf(wh[h], f1.x, a[h][1].x); a[h][1].y = fmaf(wh[h], f1.y, a[h][1].y);
            a[h][1].z = fmaf(wh[h], f1.z, a[h][1].z); a[h][1].w = fmaf(wh[h], f1.w, a[h][1].w);
        }
    }
    #pragma unroll
    for (int h = 0; h < NH; h++) {
        float* zp = g_z2 + ((size_t)i * NH + h) * FD + dbase;
        *reinterpret_cast<float4*>(zp)     = a[h][0];
        *reinterpret_cast<float4*>(zp + 4) = a[h][1];
    }
}

// ---------------- final: out[i][c] = tanh(elu(sum_k z2[i][c>>7][k]*W1[k][c] + h1p[posS[id]][c] + b[c])) ----------------
__global__ __launch_bounds__(256) void k_final(const float* __restrict__ W1,
                                               const float* __restrict__ bias1,
                                               const int* __restrict__ ids, int nIds,
                                               float* __restrict__ out) {
    int c = blockIdx.x * 32 + (threadIdx.x & 31);
    int hc = c >> 7;                       // head of this output column
    int rg = threadIdx.x >> 5;             // rows rg and rg+8
    const float* wc = W1 + c;
    const float* z0 = g_z2 + ((size_t)rg * NH + hc) * FD;
    const float* z1 = g_z2 + ((size_t)(rg + 8) * NH + hc) * FD;
    float acc0 = 0.f, acc1 = 0.f;
    for (int k = 0; k < FD; k += 4) {
        float4 a = *reinterpret_cast<const float4*>(z0 + k);
        float4 b = *reinterpret_cast<const float4*>(z1 + k);
        float w0 = wc[(size_t)(k + 0) * FD];
        float w1 = wc[(size_t)(k + 1) * FD];
        float w2 = wc[(size_t)(k + 2) * FD];
        float w3 = wc[(size_t)(k + 3) * FD];
        acc0 = fmaf(a.x, w0, acc0); acc0 = fmaf(a.y, w1, acc0);
        acc0 = fmaf(a.z, w2, acc0); acc0 = fmaf(a.w, w3, acc0);
        acc1 = fmaf(b.x, w0, acc1); acc1 = fmaf(b.y, w1, acc1);
        acc1 = fmaf(b.z, w2, acc1); acc1 = fmaf(b.w, w3, acc1);
    }
    float bv = bias1[c];
    if (rg < nIds) {
        int pv = g_posS[ids[rg]];
        float x = acc0 + g_h1p[(size_t)pv * FD + c] + bv;
        out[(size_t)rg * FD + c] = tanhf(eluf(x));
    }
    int r2 = rg + 8;
    if (r2 < nIds) {
        int pv = g_posS[ids[r2]];
        float x = acc1 + g_h1p[(size_t)pv * FD + c] + bv;
        out[(size_t)r2 * FD + c] = tanhf(eluf(x));
    }
}

// ---------------- launch ----------------
extern "C" void kernel_launch(void* const* d_in, const int* in_sizes, int n_in,
                              void* d_out, int out_size) {
    const float* features = (const float*)d_in[0];
    const float* fc_w0    = (const float*)d_in[1];
    const float* attn_l0  = (const float*)d_in[2];
    const float* attn_r0  = (const float*)d_in[3];
    const float* bias0    = (const float*)d_in[4];
    const float* fc_w1    = (const float*)d_in[5];
    const float* attn_l1  = (const float*)d_in[6];
    const float* attn_r1  = (const float*)d_in[7];
    const float* bias1    = (const float*)d_in[8];
    const int*   src      = (const int*)d_in[9];
    const int*   dst      = (const int*)d_in[10];
    const int*   ids      = (const int*)d_in[11];
    int E    = in_sizes[9];
    int nIds = in_sizes[11];
    float* out = (float*)d_out;

    k_init<<<(NN + 255) / 256, 256>>>();
    k_proj<<<128, 128>>>(fc_w0, attn_l0, attn_r0, fc_w1, attn_l1, attn_r1, ids, nIds);
    k_scan_e2<<<1024, 256>>>(src, dst, E);
    k_scan_e1<<<1024, 256>>>(src, dst, E);

    // layer 1
    k_eler0<<<256, 256>>>(features);
    k_agg1<<<148, 256>>>(features);
    k_gemm1<<<64, GT>>>(fc_w0, bias0);

    // layer 2
    k_agg2<<<2, 512>>>(ids, nIds);
    k_final<<<16, 256>>>(fc_w1, bias1, ids, nIds, out);
}

// round 12
// speedup vs baseline: 5.2954x; 1.1066x over previous
#include <cuda_runtime.h>
#include <math.h>

#define NN 50000
#define FD 512
#define NH 4

constexpr int MAX_S  = 8192;
constexpr int MAX_U  = 262144;
constexpr int MAXDEG = 128;
constexpr int MAXIDS = 32;
constexpr int NMSK   = 1600;   // ceil(50000/32) = 1563, rounded up

// ---------------- static device scratch ----------------
__device__ float4 g_el4[NN];                        // layer1 el per node (4 heads)
__device__ float4 g_er4[NN];
__device__ float  g_z[(size_t)MAX_S * NH * FD];     // per-head aggregated raw features
__device__ float  g_h1p[(size_t)MAX_S * FD];        // h1 by S-position
__device__ float4 g_el1_4[MAX_S];
__device__ float4 g_er1_4[MAX_S];
__device__ float  g_z2[(size_t)MAXIDS * NH * FD];
__device__ float4 g_wl0_4[FD], g_wr0_4[FD], g_wl1_4[FD], g_wr1_4[FD];
__device__ unsigned g_mskS[NMSK], g_mskU[NMSK];
__device__ int g_S[MAX_S], g_posS[NN], g_degS[MAX_S];
__device__ int g_bkt[(size_t)MAX_S * MAXDEG];       // SRC node of each bucketed edge
__device__ int g_U[MAX_U];
__device__ int g_nS, g_nU;

// ---------------- helpers ----------------
__device__ __forceinline__ unsigned long long dup2(float a) {
    unsigned long long r;
    unsigned int ai = __float_as_uint(a);
    asm("mov.b64 %0, {%1, %1};" : "=l"(r) : "r"(ai));
    return r;
}
__device__ __forceinline__ void fma2(unsigned long long& d, unsigned long long a, unsigned long long b) {
    asm("fma.rn.f32x2 %0, %1, %2, %0;" : "+l"(d) : "l"(a), "l"(b));
}
__device__ __forceinline__ float2 unpack2(unsigned long long v) {
    float2 r;
    r.x = __uint_as_float((unsigned int)(v & 0xffffffffull));
    r.y = __uint_as_float((unsigned int)(v >> 32));
    return r;
}
__device__ __forceinline__ float wredsum(float x) {
    #pragma unroll
    for (int o = 16; o > 0; o >>= 1) x += __shfl_xor_sync(0xffffffffu, x, o);
    return x;
}
__device__ __forceinline__ float wredmax(float x) {
    #pragma unroll
    for (int o = 16; o > 0; o >>= 1) x = fmaxf(x, __shfl_xor_sync(0xffffffffu, x, o));
    return x;
}
__device__ __forceinline__ float eluf(float x) { return (x > 0.f) ? x : expm1f(x); }

// ---------------- setup: zero scratch + projected attention vectors ----------------
__global__ __launch_bounds__(256) void k_setup(const float* __restrict__ W0,
                                               const float* __restrict__ al0, const float* __restrict__ ar0,
                                               const float* __restrict__ W1,
                                               const float* __restrict__ al1, const float* __restrict__ ar1) {
    int gi = blockIdx.x * 256 + threadIdx.x;
    // init
    if (gi < MAX_S) {
        g_degS[gi] = 0;
        g_el1_4[gi] = make_float4(0, 0, 0, 0);
        g_er1_4[gi] = make_float4(0, 0, 0, 0);
    }
    if (gi < NMSK) { g_mskS[gi] = 0; g_mskU[gi] = 0; }
    if (gi == 0) { g_nS = 0; g_nU = 0; }

    // proj: warp w computes row k=w of the four projected tables
    int lane = threadIdx.x & 31;
    int w = gi >> 5;
    if (w >= FD) return;
    const float4* w0r = reinterpret_cast<const float4*>(W0 + (size_t)w * FD);
    const float4* w1r = reinterpret_cast<const float4*>(W1 + (size_t)w * FD);
    const float4* l0 = reinterpret_cast<const float4*>(al0);
    const float4* r0 = reinterpret_cast<const float4*>(ar0);
    const float4* l1 = reinterpret_cast<const float4*>(al1);
    const float4* r1 = reinterpret_cast<const float4*>(ar1);
    float sl0[NH], sr0[NH], sl1[NH], sr1[NH];
    #pragma unroll
    for (int h = 0; h < NH; h++) {
        float4 a0 = w0r[h * 32 + lane];
        float4 b0l = l0[h * 32 + lane];
        float4 b0r = r0[h * 32 + lane];
        sl0[h] = wredsum(a0.x * b0l.x + a0.y * b0l.y + a0.z * b0l.z + a0.w * b0l.w);
        sr0[h] = wredsum(a0.x * b0r.x + a0.y * b0r.y + a0.z * b0r.z + a0.w * b0r.w);
        float4 a1 = w1r[h * 32 + lane];
        float4 b1l = l1[h * 32 + lane];
        float4 b1r = r1[h * 32 + lane];
        sl1[h] = wredsum(a1.x * b1l.x + a1.y * b1l.y + a1.z * b1l.z + a1.w * b1l.w);
        sr1[h] = wredsum(a1.x * b1r.x + a1.y * b1r.y + a1.z * b1r.z + a1.w * b1r.w);
    }
    if (lane == 0) {
        g_wl0_4[w] = make_float4(sl0[0], sl0[1], sl0[2], sl0[3]);
        g_wr0_4[w] = make_float4(sr0[0], sr0[1], sr0[2], sr0[3]);
        g_wl1_4[w] = make_float4(sl1[0], sl1[1], sl1[2], sl1[3]);
        g_wr1_4[w] = make_float4(sr1[0], sr1[1], sr1[2], sr1[3]);
    }
}

// ---------------- scan e2: edges into ids -> build S (smem id-bitmask) ----------------
__global__ __launch_bounds__(256) void k_scan_e2(const int* __restrict__ src, const int* __restrict__ dst,
                                                 const int* __restrict__ ids, int nIds, int E) {
    __shared__ unsigned smsk[NMSK];
    for (int i = threadIdx.x; i < NMSK; i += 256) smsk[i] = 0;
    __syncthreads();
    if (threadIdx.x < nIds) {
        int v = ids[threadIdx.x];
        atomicOr(&smsk[v >> 5], 1u << (v & 31));
    }
    __syncthreads();
    int i = blockIdx.x * blockDim.x + threadIdx.x;
    int stride = gridDim.x * blockDim.x;
    int E4 = E >> 2;
    const int4* d4 = reinterpret_cast<const int4*>(dst);
    auto proc = [&](int dd, int e) {
        if ((smsk[dd >> 5] >> (dd & 31)) & 1u) {
            int s = src[e];
            unsigned m = 1u << (s & 31);
            unsigned old = atomicOr(&g_mskS[s >> 5], m);
            if (!(old & m)) {
                int p = atomicAdd(&g_nS, 1);
                if (p < MAX_S) { g_S[p] = s; g_posS[s] = p; }
            }
        }
    };
    for (int q = i; q < E4; q += stride) {
        int4 d = d4[q];
        int e = q * 4;
        proc(d.x, e); proc(d.y, e + 1); proc(d.z, e + 2); proc(d.w, e + 3);
    }
    for (int e = E4 * 4 + i; e < E; e += stride) proc(dst[e], e);
}

// ---------------- scan e1: bucket edges into S (smem S-bitmask); build U ----------------
__global__ __launch_bounds__(256) void k_scan_e1(const int* __restrict__ src, const int* __restrict__ dst, int E) {
    __shared__ unsigned smsk[NMSK];
    for (int i = threadIdx.x; i < NMSK; i += 256) smsk[i] = g_mskS[i];
    __syncthreads();
    int i = blockIdx.x * blockDim.x + threadIdx.x;
    int stride = gridDim.x * blockDim.x;
    int E4 = E >> 2;
    const int4* d4 = reinterpret_cast<const int4*>(dst);
    auto proc = [&](int dd, int e) {
        if ((smsk[dd >> 5] >> (dd & 31)) & 1u) {
            int p = g_posS[dd];
            int s = src[e];
            int slot = atomicAdd(&g_degS[p], 1);
            if (slot < MAXDEG) g_bkt[(size_t)p * MAXDEG + slot] = s;
            unsigned m = 1u << (s & 31);
            if (!((g_mskU[s >> 5] >> (s & 31)) & 1u)) {
                unsigned old = atomicOr(&g_mskU[s >> 5], m);
                if (!(old & m)) {
                    int u = atomicAdd(&g_nU, 1);
                    if (u < MAX_U) g_U[u] = s;
                }
            }
        }
    };
    for (int q = i; q < E4; q += stride) {
        int4 d = d4[q];
        int e = q * 4;
        proc(d.x, e); proc(d.y, e + 1); proc(d.z, e + 2); proc(d.w, e + 3);
    }
    for (int e = E4 * 4 + i; e < E; e += stride) proc(dst[e], e);
}

// ---------------- el/er for layer 1 over U (smem-staged tables) ----------------
__global__ __launch_bounds__(256) void k_eler0(const float* __restrict__ X) {
    __shared__ float4 swl[FD], swr[FD];
    for (int k = threadIdx.x; k < FD; k += 256) { swl[k] = g_wl0_4[k]; swr[k] = g_wr0_4[k]; }
    __syncthreads();
    int lane = threadIdx.x & 31;
    int w = (blockIdx.x * blockDim.x + threadIdx.x) >> 5;
    int nw = (gridDim.x * blockDim.x) >> 5;
    int n = min(g_nU, MAX_U);
    for (int g = w; g < n; g += nw) {
        int v = g_U[g];
        const float4* xr = reinterpret_cast<const float4*>(X + (size_t)v * FD);
        float aL[NH] = {0, 0, 0, 0}, aR[NH] = {0, 0, 0, 0};
        #pragma unroll
        for (int i = 0; i < 4; i++) {
            float4 x4 = xr[lane * 4 + i];
            float xs[4] = {x4.x, x4.y, x4.z, x4.w};
            #pragma unroll
            for (int c = 0; c < 4; c++) {
                int k = lane * 16 + i * 4 + c;
                float4 l4 = swl[k];
                float4 r4 = swr[k];
                aL[0] = fmaf(xs[c], l4.x, aL[0]); aL[1] = fmaf(xs[c], l4.y, aL[1]);
                aL[2] = fmaf(xs[c], l4.z, aL[2]); aL[3] = fmaf(xs[c], l4.w, aL[3]);
                aR[0] = fmaf(xs[c], r4.x, aR[0]); aR[1] = fmaf(xs[c], r4.y, aR[1]);
                aR[2] = fmaf(xs[c], r4.z, aR[2]); aR[3] = fmaf(xs[c], r4.w, aR[3]);
            }
        }
        #pragma unroll
        for (int h = 0; h < NH; h++) { aL[h] = wredsum(aL[h]); aR[h] = wredsum(aR[h]); }
        if (lane == 0) {
            g_el4[v] = make_float4(aL[0], aL[1], aL[2], aL[3]);
            g_er4[v] = make_float4(aR[0], aR[1], aR[2], aR[3]);
        }
    }
}

// ---------------- layer-1 per-head aggregation; block = 4 dsts, scores shared ----------------
__global__ __launch_bounds__(256) void k_agg1(const float* __restrict__ X) {
    __shared__ int   ssrc[4][MAXDEG];
    __shared__ float ssc[4][MAXDEG][NH];
    __shared__ float sinv[4][NH];
    int w = threadIdx.x >> 5, lane = threadIdx.x & 31;
    int nS = min(g_nS, MAX_S);
    int nGrp = (nS + 3) >> 2;
    for (int grp = blockIdx.x; grp < nGrp; grp += gridDim.x) {
        if (w < 4) {
            int p = grp * 4 + w;
            if (p < nS) {
                int v = g_S[p];
                int cnt = min(g_degS[p], MAXDEG);
                float4 er4 = g_er4[v];
                float erv[NH] = {er4.x, er4.y, er4.z, er4.w};
                float mx[NH] = {-1e30f, -1e30f, -1e30f, -1e30f};
                for (int j = lane; j < cnt; j += 32) {
                    int s = g_bkt[(size_t)p * MAXDEG + j];
                    ssrc[w][j] = s;
                    float4 el4 = g_el4[s];
                    float es[4] = {el4.x, el4.y, el4.z, el4.w};
                    #pragma unroll
                    for (int h = 0; h < NH; h++) {
                        float x = es[h] + erv[h];
                        x = (x > 0.f) ? x : 0.2f * x;
                        ssc[w][j][h] = x;
                        mx[h] = fmaxf(mx[h], x);
                    }
                }
                #pragma unroll
                for (int h = 0; h < NH; h++) mx[h] = wredmax(mx[h]);
                __syncwarp();
                float sm[NH] = {0.f, 0.f, 0.f, 0.f};
                for (int j = lane; j < cnt; j += 32) {
                    #pragma unroll
                    for (int h = 0; h < NH; h++) {
                        float ex = expf(ssc[w][j][h] - mx[h]);
                        ssc[w][j][h] = ex;
                        sm[h] += ex;
                    }
                }
                #pragma unroll
                for (int h = 0; h < NH; h++) {
                    float s = wredsum(sm[h]);
                    if (lane == 0) sinv[w][h] = 1.f / s;
                }
            }
        }
        __syncthreads();
        {
            int slot = w >> 1;
            int p = grp * 4 + slot;
            if (p < nS) {
                int half = w & 1;
                int cnt = min(g_degS[p], MAXDEG);
                float inv[NH];
                #pragma unroll
                for (int h = 0; h < NH; h++) inv[h] = sinv[slot][h];
                int dbase = half * 256 + lane * 8;
                float4 a[NH][2];
                #pragma unroll
                for (int h = 0; h < NH; h++) { a[h][0] = make_float4(0, 0, 0, 0); a[h][1] = make_float4(0, 0, 0, 0); }
                for (int j = 0; j < cnt; j++) {
                    int s = ssrc[slot][j];
                    float wh[NH];
                    #pragma unroll
                    for (int h = 0; h < NH; h++) wh[h] = ssc[slot][j][h] * inv[h];
                    const float4* xp = reinterpret_cast<const float4*>(X + (size_t)s * FD + dbase);
                    float4 f0 = xp[0], f1 = xp[1];
                    #pragma unroll
                    for (int h = 0; h < NH; h++) {
                        a[h][0].x = fmaf(wh[h], f0.x, a[h][0].x); a[h][0].y = fmaf(wh[h], f0.y, a[h][0].y);
                        a[h][0].z = fmaf(wh[h], f0.z, a[h][0].z); a[h][0].w = fmaf(wh[h], f0.w, a[h][0].w);
                        a[h][1].x = fmaf(wh[h], f1.x, a[h][1].x); a[h][1].y = fmaf(wh[h], f1.y, a[h][1].y);
                        a[h][1].z = fmaf(wh[h], f1.z, a[h][1].z); a[h][1].w = fmaf(wh[h], f1.w, a[h][1].w);
                    }
                }
                #pragma unroll
                for (int h = 0; h < NH; h++) {
                    float* zp = g_z + ((size_t)p * NH + h) * FD + dbase;
                    *reinterpret_cast<float4*>(zp)     = a[h][0];
                    *reinterpret_cast<float4*>(zp + 4) = a[h][1];
                }
            }
        }
        __syncthreads();
    }
}

// ---------------- layer-1 head-blocked GEMM + fused el1/er1 epilogue ----------------
constexpr int BN = 128, BK = 16, GT = 256;

__global__ __launch_bounds__(GT) void k_gemm1(const float* __restrict__ W,
                                              const float* __restrict__ bias) {
    constexpr int RPT = 4, BM = 64, ALD = 4, WLD = 8;
    __shared__ __align__(16) float As[2][BK][BM + 4];
    __shared__ __align__(16) float Ws[2][BK][BN + 4];
    float* C = g_h1p;
    int nRows = min(g_nS, MAX_S);
    int nRT = (nRows + BM - 1) / BM;
    int nTiles = nRT * (FD / BN);
    int tid = threadIdx.x;
    int tr = tid >> 4, tc = tid & 15;
    int wc = tid & 127, wk0 = tid >> 7;
    int woff[WLD];
    #pragma unroll
    for (int i = 0; i < WLD; i++) woff[i] = (wk0 + i * 2) * FD + wc;

    for (int t = blockIdx.x; t < nTiles; t += gridDim.x) {
        int rt = t >> 2, ct = t & 3;              // ct == head
        int rbase = rt * BM, cbase = ct * BN;
        const float* aptr[ALD];
        #pragma unroll
        for (int i = 0; i < ALD; i++) {
            int gr = rbase + tr + i * 16;
            aptr[i] = (gr < nRows) ? (g_z + ((size_t)gr * NH + ct) * FD) : nullptr;
        }
        const float* wbase = W + cbase;

        unsigned long long acc[RPT][4];
        #pragma unroll
        for (int r = 0; r < RPT; r++)
            #pragma unroll
            for (int c = 0; c < 4; c++) acc[r][c] = 0ull;

        float aReg[ALD], wReg[WLD];
        #pragma unroll
        for (int i = 0; i < ALD; i++) aReg[i] = aptr[i] ? aptr[i][tc] : 0.f;
        #pragma unroll
        for (int i = 0; i < WLD; i++) wReg[i] = wbase[woff[i]];
        #pragma unroll
        for (int i = 0; i < ALD; i++) As[0][tc][tr + i * 16] = aReg[i];
        #pragma unroll
        for (int i = 0; i < WLD; i++) Ws[0][wk0 + i * 2][wc] = wReg[i];
        __syncthreads();

        int buf = 0;
        for (int kc = 0; kc < FD; kc += BK) {
            bool more = (kc + BK) < FD;
            if (more) {
                int kn = kc + BK;
                #pragma unroll
                for (int i = 0; i < ALD; i++) aReg[i] = aptr[i] ? aptr[i][kn + tc] : 0.f;
                #pragma unroll
                for (int i = 0; i < WLD; i++) wReg[i] = wbase[(size_t)kn * FD + woff[i]];
            }
            #pragma unroll
            for (int kk = 0; kk < BK; kk++) {
                float4 av = *reinterpret_cast<const float4*>(&As[buf][kk][tr * 4]);
                unsigned long long ad[4] = {dup2(av.x), dup2(av.y), dup2(av.z), dup2(av.w)};
                ulonglong2 b0 = *reinterpret_cast<const ulonglong2*>(&Ws[buf][kk][tc * 8]);
                ulonglong2 b1 = *reinterpret_cast<const ulonglong2*>(&Ws[buf][kk][tc * 8 + 4]);
                unsigned long long bp[4] = {b0.x, b0.y, b1.x, b1.y};
                #pragma unroll
                for (int r = 0; r < RPT; r++)
                    #pragma unroll
                    for (int c = 0; c < 4; c++)
                        fma2(acc[r][c], ad[r], bp[c]);
            }
            __syncthreads();
            if (more) {
                #pragma unroll
                for (int i = 0; i < ALD; i++) As[buf ^ 1][tc][tr + i * 16] = aReg[i];
                #pragma unroll
                for (int i = 0; i < WLD; i++) Ws[buf ^ 1][wk0 + i * 2][wc] = wReg[i];
            }
            __syncthreads();
            buf ^= 1;
        }

        const float4* b4 = reinterpret_cast<const float4*>(bias + cbase + tc * 8);
        float4 bb0 = b4[0], bb1 = b4[1];
        float4 wl[8], wr[8];
        #pragma unroll
        for (int i = 0; i < 8; i++) {
            wl[i] = g_wl1_4[cbase + tc * 8 + i];
            wr[i] = g_wr1_4[cbase + tc * 8 + i];
        }
        #pragma unroll
        for (int r = 0; r < RPT; r++) {
            int gr = rbase + tr * 4 + r;
            if (gr < nRows) {
                float2 p0 = unpack2(acc[r][0]);
                float2 p1 = unpack2(acc[r][1]);
                float2 p2 = unpack2(acc[r][2]);
                float2 p3 = unpack2(acc[r][3]);
                float vals[8] = {eluf(p0.x + bb0.x), eluf(p0.y + bb0.y),
                                 eluf(p1.x + bb0.z), eluf(p1.y + bb0.w),
                                 eluf(p2.x + bb1.x), eluf(p2.y + bb1.y),
                                 eluf(p3.x + bb1.z), eluf(p3.y + bb1.w)};
                float* cp = C + (size_t)gr * FD + cbase + tc * 8;
                *reinterpret_cast<float4*>(cp)     = make_float4(vals[0], vals[1], vals[2], vals[3]);
                *reinterpret_cast<float4*>(cp + 4) = make_float4(vals[4], vals[5], vals[6], vals[7]);
                float l0 = 0, l1 = 0, l2 = 0, l3 = 0, r0 = 0, r1 = 0, r2 = 0, r3 = 0;
                #pragma unroll
                for (int i = 0; i < 8; i++) {
                    l0 = fmaf(vals[i], wl[i].x, l0); l1 = fmaf(vals[i], wl[i].y, l1);
                    l2 = fmaf(vals[i], wl[i].z, l2); l3 = fmaf(vals[i], wl[i].w, l3);
                    r0 = fmaf(vals[i], wr[i].x, r0); r1 = fmaf(vals[i], wr[i].y, r1);
                    r2 = fmaf(vals[i], wr[i].z, r2); r3 = fmaf(vals[i], wr[i].w, r3);
                }
                float* elp = reinterpret_cast<float*>(&g_el1_4[gr]);
                float* erp = reinterpret_cast<float*>(&g_er1_4[gr]);
                atomicAdd(elp + 0, l0); atomicAdd(elp + 1, l1);
                atomicAdd(elp + 2, l2); atomicAdd(elp + 3, l3);
                atomicAdd(erp + 0, r0); atomicAdd(erp + 1, r1);
                atomicAdd(erp + 2, r2); atomicAdd(erp + 3, r3);
            }
        }
    }
}

// ---------------- layer-2 per-head aggregation (bucket-based: ids are in S) ----------------
__global__ __launch_bounds__(512) void k_agg2(const int* __restrict__ ids, int nIds) {
    __shared__ int   sps[16][MAXDEG];
    __shared__ float ssc[16][MAXDEG][NH];
    int wslot = threadIdx.x >> 5, lane = threadIdx.x & 31;
    int item = blockIdx.x * 16 + wslot;
    if (item >= nIds * 2) return;
    int i = item >> 1, half = item & 1;
    int v = ids[i];
    int pv = g_posS[v];
    int cnt = min(g_degS[pv], MAXDEG);

    float4 er4 = g_er1_4[pv];
    float erv[NH] = {er4.x, er4.y, er4.z, er4.w};
    float mx[NH] = {-1e30f, -1e30f, -1e30f, -1e30f};
    for (int j = lane; j < cnt; j += 32) {
        int s = g_bkt[(size_t)pv * MAXDEG + j];
        int ps = g_posS[s];
        sps[wslot][j] = ps;
        float4 el4 = g_el1_4[ps];
        float es[4] = {el4.x, el4.y, el4.z, el4.w};
        #pragma unroll
        for (int h = 0; h < NH; h++) {
            float x = es[h] + erv[h];
            x = (x > 0.f) ? x : 0.2f * x;
            ssc[wslot][j][h] = x;
            mx[h] = fmaxf(mx[h], x);
        }
    }
    #pragma unroll
    for (int h = 0; h < NH; h++) mx[h] = wredmax(mx[h]);
    __syncwarp();
    float sm[NH] = {0.f, 0.f, 0.f, 0.f};
    for (int j = lane; j < cnt; j += 32) {
        #pragma unroll
        for (int h = 0; h < NH; h++) {
            float ex = expf(ssc[wslot][j][h] - mx[h]);
            ssc[wslot][j][h] = ex;
            sm[h] += ex;
        }
    }
    float inv[NH];
    #pragma unroll
    for (int h = 0; h < NH; h++) inv[h] = 1.f / wredsum(sm[h]);
    __syncwarp();

    int dbase = half * 256 + lane * 8;
    float4 a[NH][2];
    #pragma unroll
    for (int h = 0; h < NH; h++) { a[h][0] = make_float4(0, 0, 0, 0); a[h][1] = make_float4(0, 0, 0, 0); }
    for (int j = 0; j < cnt; j++) {
        int ps = sps[wslot][j];
        float wh[NH];
        #pragma unroll
        for (int h = 0; h < NH; h++) wh[h] = ssc[wslot][j][h] * inv[h];
        const float4* fp = reinterpret_cast<const float4*>(g_h1p + (size_t)ps * FD + dbase);
        float4 f0 = fp[0], f1 = fp[1];
        #pragma unroll
        for (int h = 0; h < NH; h++) {
            a[h][0].x = fmaf(wh[h], f0.x, a[h][0].x); a[h][0].y = fmaf(wh[h], f0.y, a[h][0].y);
            a[h][0].z = fmaf(wh[h], f0.z, a[h][0].z); a[h][0].w = fmaf(wh[h], f0.w, a[h][0].w);
            a[h][1].x = fmaf(wh[h], f1.x, a[h][1].x); a[h][1].y = fmaf(wh[h], f1.y, a[h][1].y);
            a[h][1].z = fmaf(wh[h], f1.z, a[h][1].z); a[h][1].w = fmaf(wh[h], f1.w, a[h][1].w);
        }
    }
    #pragma unroll
    for (int h = 0; h < NH; h++) {
        float* zp = g_z2 + ((size_t)i * NH + h) * FD + dbase;
        *reinterpret_cast<float4*>(zp)     = a[h][0];
        *reinterpret_cast<float4*>(zp + 4) = a[h][1];
    }
}

// ---------------- final: out[i][c] = tanh(elu(sum_k z2[i][c>>7][k]*W1[k][c] + h1p[posS[id]][c] + b[c])) ----------------
__global__ __launch_bounds__(256) void k_final(const float* __restrict__ W1,
                                               const float* __restrict__ bias1,
                                               const int* __restrict__ ids, int nIds,
                                               float* __restrict__ out) {
    int c = blockIdx.x * 32 + (threadIdx.x & 31);
    int hc = c >> 7;                       // head of this output column
    int rg = threadIdx.x >> 5;             // rows rg and rg+8
    const float* wc = W1 + c;
    const float* z0 = g_z2 + ((size_t)rg * NH + hc) * FD;
    const float* z1 = g_z2 + ((size_t)(rg + 8) * NH + hc) * FD;
    float acc0 = 0.f, acc1 = 0.f;
    for (int k = 0; k < FD; k += 4) {
        float4 a = *reinterpret_cast<const float4*>(z0 + k);
        float4 b = *reinterpret_cast<const float4*>(z1 + k);
        float w0 = wc[(size_t)(k + 0) * FD];
        float w1 = wc[(size_t)(k + 1) * FD];
        float w2 = wc[(size_t)(k + 2) * FD];
        float w3 = wc[(size_t)(k + 3) * FD];
        acc0 = fmaf(a.x, w0, acc0); acc0 = fmaf(a.y, w1, acc0);
        acc0 = fmaf(a.z, w2, acc0); acc0 = fmaf(a.w, w3, acc0);
        acc1 = fmaf(b.x, w0, acc1); acc1 = fmaf(b.y, w1, acc1);
        acc1 = fmaf(b.z, w2, acc1); acc1 = fmaf(b.w, w3, acc1);
    }
    float bv = bias1[c];
    if (rg < nIds) {
        int pv = g_posS[ids[rg]];
        float x = acc0 + g_h1p[(size_t)pv * FD + c] + bv;
        out[(size_t)rg * FD + c] = tanhf(eluf(x));
    }
    int r2 = rg + 8;
    if (r2 < nIds) {
        int pv = g_posS[ids[r2]];
        float x = acc1 + g_h1p[(size_t)pv * FD + c] + bv;
        out[(size_t)r2 * FD + c] = tanhf(eluf(x));
    }
}

// ---------------- launch ----------------
extern "C" void kernel_launch(void* const* d_in, const int* in_sizes, int n_in,
                              void* d_out, int out_size) {
    const float* features = (const float*)d_in[0];
    const float* fc_w0    = (const float*)d_in[1];
    const float* attn_l0  = (const float*)d_in[2];
    const float* attn_r0  = (const float*)d_in[3];
    const float* bias0    = (const float*)d_in[4];
    const float* fc_w1    = (const float*)d_in[5];
    const float* attn_l1  = (const float*)d_in[6];
    const float* attn_r1  = (const float*)d_in[7];
    const float* bias1    = (const float*)d_in[8];
    const int*   src      = (const int*)d_in[9];
    const int*   dst      = (const int*)d_in[10];
    const int*   ids      = (const int*)d_in[11];
    int E    = in_sizes[9];
    int nIds = in_sizes[11];
    float* out = (float*)d_out;

    k_setup<<<128, 256>>>(fc_w0, attn_l0, attn_r0, fc_w1, attn_l1, attn_r1);
    k_scan_e2<<<1184, 256>>>(src, dst, ids, nIds, E);
    k_scan_e1<<<1184, 256>>>(src, dst, E);

    // layer 1
    k_eler0<<<256, 256>>>(features);
    k_agg1<<<148, 256>>>(features);
    k_gemm1<<<64, GT>>>(fc_w0, bias0);

    // layer 2
    k_agg2<<<2, 512>>>(ids, nIds);
    k_final<<<16, 256>>>(fc_w1, bias1, ids, nIds, out);
}